// round 10
// baseline (speedup 1.0000x reference)
#include <cuda_runtime.h>
#include <cuda_bf16.h>
#include <math.h>
#include <stdint.h>

#define BB   32
#define LL   1024
#define DIN  2048
#define HH   1024
#define NLB  21
#define EE   768
#define MM   (BB*LL)
#define LN_EPS 1e-5f

// ---------------- device scratch ----------------
__device__ __align__(16) float g_h[(size_t)MM * HH];
__device__ __align__(16) __nv_bfloat16 g_ahi[(size_t)MM * DIN];
__device__ __align__(16) __nv_bfloat16 g_alo[(size_t)MM * DIN];
__device__ __align__(16) __nv_bfloat16 g_bhi[(size_t)HH * DIN];   // [n][k]
__device__ __align__(16) __nv_bfloat16 g_blo[(size_t)HH * DIN];
__device__ __align__(16) float g_labelh[NLB * HH];
__device__ __align__(16) float g_rowmax[MM];
__device__ float g_nll[BB];

// ---------------- helpers ----------------
__device__ __forceinline__ uint32_t smem_u32(const void* p) {
    uint32_t a;
    asm("{ .reg .u64 t; cvta.to.shared.u64 t, %1; cvt.u32.u64 %0, t; }" : "=r"(a) : "l"(p));
    return a;
}
#define CP16(ds, sp) asm volatile("cp.async.cg.shared.global [%0], [%1], 16;" \
    :: "r"(ds), "l"(__cvta_generic_to_global(sp)) : "memory")
#define CP_COMMIT() asm volatile("cp.async.commit_group;" ::: "memory")
#define LDSM_X4(r0, r1, r2, r3, a) asm volatile( \
    "ldmatrix.sync.aligned.m8n8.x4.shared.b16 {%0,%1,%2,%3}, [%4];" \
    : "=r"(r0), "=r"(r1), "=r"(r2), "=r"(r3) : "r"(a))
#define MMA4(d, a0, a1, a2, a3, b0, b1) asm volatile( \
    "mma.sync.aligned.m16n8k16.row.col.f32.bf16.bf16.f32 " \
    "{%0,%1,%2,%3}, {%4,%5,%6,%7}, {%8,%9}, {%0,%1,%2,%3};" \
    : "+f"((d)[0]), "+f"((d)[1]), "+f"((d)[2]), "+f"((d)[3]) \
    : "r"(a0), "r"(a1), "r"(a2), "r"(a3), "r"(b0), "r"(b1))

// ---------------- split kernels ----------------
__global__ void ksplitA(const float* __restrict__ X) {
    size_t i = ((size_t)blockIdx.x * blockDim.x + threadIdx.x) * 4;
    float4 v = *(const float4*)(X + i);
    __nv_bfloat16 h0 = __float2bfloat16(v.x), h1 = __float2bfloat16(v.y);
    __nv_bfloat16 h2 = __float2bfloat16(v.z), h3 = __float2bfloat16(v.w);
    __nv_bfloat16 l0 = __float2bfloat16(v.x - __bfloat162float(h0));
    __nv_bfloat16 l1 = __float2bfloat16(v.y - __bfloat162float(h1));
    __nv_bfloat16 l2 = __float2bfloat16(v.z - __bfloat162float(h2));
    __nv_bfloat16 l3 = __float2bfloat16(v.w - __bfloat162float(h3));
    *(__nv_bfloat162*)(g_ahi + i)     = __nv_bfloat162(h0, h1);
    *(__nv_bfloat162*)(g_ahi + i + 2) = __nv_bfloat162(h2, h3);
    *(__nv_bfloat162*)(g_alo + i)     = __nv_bfloat162(l0, l1);
    *(__nv_bfloat162*)(g_alo + i + 2) = __nv_bfloat162(l2, l3);
}

__global__ void ksplitB(const float* __restrict__ W) {
    __shared__ float tile[32][33];
    const int kb = blockIdx.x * 32, nb = blockIdx.y * 32;
    const int tx = threadIdx.x, ty = threadIdx.y;  // 32 x 8
    #pragma unroll
    for (int i = 0; i < 32; i += 8)
        tile[ty + i][tx] = W[(size_t)(kb + ty + i) * HH + nb + tx];
    __syncthreads();
    #pragma unroll
    for (int i = 0; i < 32; i += 8) {
        float v = tile[tx][ty + i];   // W[kb+tx][nb+ty+i]
        __nv_bfloat16 hi = __float2bfloat16(v);
        __nv_bfloat16 lo = __float2bfloat16(v - __bfloat162float(hi));
        size_t o = (size_t)(nb + ty + i) * DIN + kb + tx;
        g_bhi[o] = hi; g_blo[o] = lo;
    }
}

// ---------------- K0: label_h ----------------
__global__ void k0_labelh(const float* __restrict__ lt, const float* __restrict__ wl) {
    const int n = blockIdx.y;
    const int h = blockIdx.x * 128 + threadIdx.x;
    float acc = 0.f;
    const float* ltr = lt + n * EE;
    #pragma unroll 4
    for (int e = 0; e < EE; e++) acc = fmaf(ltr[e], wl[(size_t)e * HH + h], acc);
    g_labelh[n * HH + h] = acc;
}

// ---------------- K1: bf16-split GEMM, 128x128 tile, 256 thr, KC=32, 2 CTA/SM ----------------
#define KC3 32
#define NCH3 (DIN / KC3)      // 64
#define TP3 80                // smem row pitch bytes
#define TILE3 (128 * TP3)     // 10240 per matrix tile
#define STAGE3 (4 * TILE3)    // 40960 per stage

__device__ __forceinline__ void prefetch3(uint32_t sbuf, int cRow, int cCol,
                                          int k0, int tid) {
    #pragma unroll
    for (int q = 0; q < 8; q++) {
        const int id = q * 256 + tid;           // 0..2047
        const int tl = id >> 9;                 // 0..3
        const int idx = id & 511;
        const int r = idx >> 2, c4 = idx & 3;
        const __nv_bfloat16* src = (tl == 0) ? g_ahi : (tl == 1) ? g_alo
                                  : (tl == 2) ? g_bhi : g_blo;
        const int rbase = (tl < 2) ? cRow : cCol;
        const uint32_t dof = sbuf + (uint32_t)(tl * TILE3 + r * TP3 + c4 * 16);
        CP16(dof, src + (size_t)(rbase + r) * DIN + k0 + c4 * 8);
    }
}

__global__ __launch_bounds__(256, 2) void k1_mma() {
    extern __shared__ char sm[];
    const int tid = threadIdx.x, lane = tid & 31, wid = tid >> 5;
    const int cCol = blockIdx.x * 128, cRow = blockIdx.y * 128;
    const int wm = wid >> 1, wn = wid & 1;  // warp tile 32M x 64N
    const uint32_t sb = smem_u32(sm);

    float acc[2][8][4];
    #pragma unroll
    for (int i = 0; i < 2; i++)
        #pragma unroll
        for (int j = 0; j < 8; j++)
            #pragma unroll
            for (int k = 0; k < 4; k++) acc[i][j][k] = 0.f;

    prefetch3(sb, cRow, cCol, 0, tid);
    CP_COMMIT();

    const int aRow = wm * 32 + (lane & 15);            // + mt*16
    const uint32_t aKb = (uint32_t)((lane >> 4) * 16); // + ks*32
    const int bRow = wn * 64 + ((lane >> 4) & 1) * 8 + (lane & 7); // + p*16
    const uint32_t bKb = (uint32_t)(((lane >> 3) & 1) * 16);

    for (int c = 0; c < NCH3; c++) {
        if (c + 1 < NCH3) {
            prefetch3(sb + (uint32_t)(((c + 1) & 1) * STAGE3), cRow, cCol,
                      (c + 1) * KC3, tid);
            CP_COMMIT();
            asm volatile("cp.async.wait_group 1;" ::: "memory");
        } else {
            asm volatile("cp.async.wait_group 0;" ::: "memory");
        }
        __syncthreads();
        const uint32_t st = sb + (uint32_t)((c & 1) * STAGE3);

        #pragma unroll
        for (int ks = 0; ks < 2; ks++) {
            uint32_t ah[2][4], al[2][4];
            #pragma unroll
            for (int mt = 0; mt < 2; mt++) {
                const uint32_t ao = st + (uint32_t)((aRow + mt * 16) * TP3) + aKb + (uint32_t)(ks * 32);
                LDSM_X4(ah[mt][0], ah[mt][1], ah[mt][2], ah[mt][3], ao);
                LDSM_X4(al[mt][0], al[mt][1], al[mt][2], al[mt][3], ao + TILE3);
            }
            #pragma unroll
            for (int p = 0; p < 4; p++) {
                const uint32_t bo = st + 2u * TILE3 +
                    (uint32_t)((bRow + p * 16) * TP3) + bKb + (uint32_t)(ks * 32);
                uint32_t bh0, bh1, bh2, bh3, bl0, bl1, bl2, bl3;
                LDSM_X4(bh0, bh1, bh2, bh3, bo);
                LDSM_X4(bl0, bl1, bl2, bl3, bo + TILE3);
                #pragma unroll
                for (int mt = 0; mt < 2; mt++) {
                    MMA4(acc[mt][2*p],   ah[mt][0], ah[mt][1], ah[mt][2], ah[mt][3], bh0, bh1);
                    MMA4(acc[mt][2*p],   ah[mt][0], ah[mt][1], ah[mt][2], ah[mt][3], bl0, bl1);
                    MMA4(acc[mt][2*p],   al[mt][0], al[mt][1], al[mt][2], al[mt][3], bh0, bh1);
                    MMA4(acc[mt][2*p+1], ah[mt][0], ah[mt][1], ah[mt][2], ah[mt][3], bh2, bh3);
                    MMA4(acc[mt][2*p+1], ah[mt][0], ah[mt][1], ah[mt][2], ah[mt][3], bl2, bl3);
                    MMA4(acc[mt][2*p+1], al[mt][0], al[mt][1], al[mt][2], al[mt][3], bh2, bh3);
                }
            }
        }
        __syncthreads();
    }

    #pragma unroll
    for (int mt = 0; mt < 2; mt++)
        #pragma unroll
        for (int nt = 0; nt < 8; nt++) {
            const int row = cRow + wm * 32 + mt * 16 + (lane >> 2);
            const int col = cCol + wn * 64 + nt * 8 + (lane & 3) * 2;
            float2 v0 = make_float2(acc[mt][nt][0], acc[mt][nt][1]);
            float2 v1 = make_float2(acc[mt][nt][2], acc[mt][nt][3]);
            *(float2*)&g_h[(size_t)row * HH + col] = v0;
            *(float2*)&g_h[(size_t)(row + 8) * HH + col] = v1;
        }
}

// ---------------- K2: warp-per-row LN + exact GELU + logits + rowmax ----------------
__global__ __launch_bounds__(256)
void k2_fused(const float* __restrict__ gamma, const float* __restrict__ beta,
              const float* __restrict__ temp_p, float* __restrict__ logits) {
    extern __shared__ float slh[];   // NLB*HH floats
    const int tid = threadIdx.x, lane = tid & 31, wid = tid >> 5;

    const float4* lh4 = (const float4*)g_labelh;
    float4* slh4 = (float4*)slh;
    #pragma unroll
    for (int i = tid; i < NLB * HH / 4; i += 256) slh4[i] = lh4[i];
    const float tempv = *temp_p;
    const float4* gamma4 = (const float4*)gamma;
    const float4* beta4  = (const float4*)beta;
    __syncthreads();

    const int rowbase = blockIdx.x * 64 + wid * 8;
    for (int r = 0; r < 8; r++) {
        const int row = rowbase + r;
        const float4* hr4 = (const float4*)(g_h + (size_t)row * HH);
        float4 xv[8];
        #pragma unroll
        for (int q = 0; q < 8; q++) xv[q] = hr4[lane + 32 * q];

        float s = 0.f, ss = 0.f;
        #pragma unroll
        for (int q = 0; q < 8; q++) {
            s  += xv[q].x + xv[q].y + xv[q].z + xv[q].w;
            ss += xv[q].x*xv[q].x + xv[q].y*xv[q].y + xv[q].z*xv[q].z + xv[q].w*xv[q].w;
        }
        #pragma unroll
        for (int o = 16; o > 0; o >>= 1) {
            s  += __shfl_xor_sync(0xffffffffu, s, o);
            ss += __shfl_xor_sync(0xffffffffu, ss, o);
        }
        const float mean = s * (1.f / HH);
        const float rstd = rsqrtf(ss * (1.f / HH) - mean * mean + LN_EPS);

        float acc[NLB];
        #pragma unroll
        for (int l = 0; l < NLB; l++) acc[l] = 0.f;

        #pragma unroll
        for (int q = 0; q < 8; q++) {
            const float4 g4 = gamma4[lane + 32 * q];
            const float4 b4 = beta4[lane + 32 * q];
            float y0 = (xv[q].x - mean) * rstd * g4.x + b4.x;
            float y1 = (xv[q].y - mean) * rstd * g4.y + b4.y;
            float y2 = (xv[q].z - mean) * rstd * g4.z + b4.z;
            float y3 = (xv[q].w - mean) * rstd * g4.w + b4.w;
            const float t0 = 0.5f * y0 * (1.f + erff(y0 * 0.70710678118654752f));
            const float t1 = 0.5f * y1 * (1.f + erff(y1 * 0.70710678118654752f));
            const float t2 = 0.5f * y2 * (1.f + erff(y2 * 0.70710678118654752f));
            const float t3 = 0.5f * y3 * (1.f + erff(y3 * 0.70710678118654752f));
            #pragma unroll
            for (int l = 0; l < NLB; l++) {
                const float4 w4 = slh4[l * 256 + lane + 32 * q];
                acc[l] = fmaf(t0, w4.x, fmaf(t1, w4.y, fmaf(t2, w4.z, fmaf(t3, w4.w, acc[l]))));
            }
        }

        float out = 0.f;
        #pragma unroll
        for (int l = 0; l < NLB; l++) {
            float v = acc[l];
            #pragma unroll
            for (int o = 16; o > 0; o >>= 1) v += __shfl_xor_sync(0xffffffffu, v, o);
            if (lane == l) out = v * tempv;
        }
        if (lane < NLB) logits[(size_t)row * NLB + lane] = out;
        float mv = (lane < NLB) ? out : -INFINITY;
        #pragma unroll
        for (int o = 16; o > 0; o >>= 1) mv = fmaxf(mv, __shfl_xor_sync(0xffffffffu, mv, o));
        if (lane == 0) g_rowmax[row] = mv;
    }
}

// ---------------- K3: CRF forward, cp.async-staged, exp domain, renorm /8 ----------------
#define CRF_CH 32                       // steps per chunk
#define CRF_NC (LL / CRF_CH)            // 32 chunks
#define CRF_FB (CRF_CH * NLB)           // 672 logits floats per chunk
#define CRF_BF (CRF_FB + CRF_CH)        // +32 rowmax = 704 floats

__global__ void k3_crf(const float* __restrict__ logits, const int* __restrict__ labels,
                       const float* __restrict__ start_t, const float* __restrict__ end_t,
                       const float* __restrict__ trans) {
    __shared__ __align__(16) float sbuf[3][CRF_BF];
    const int b = blockIdx.x;
    const int j = threadIdx.x;  // 32 lanes
    float eT[NLB];
    #pragma unroll
    for (int i = 0; i < NLB; i++) eT[i] = (j < NLB) ? expf(trans[i * NLB + j]) : 0.f;

    const float* lg = logits + (size_t)b * LL * NLB;
    const float* rm = g_rowmax + (size_t)b * LL;
    const int* lab = labels + (size_t)b * LL;

    const char* lgB = (const char*)lg;
    const char* rmB = (const char*)rm;

    #pragma unroll
    for (int cc = 0; cc < 2; cc++) {
        const uint32_t dst = smem_u32(&sbuf[cc][0]);
        for (int u = j; u < 176; u += 32) {
            const char* src = (u < 168) ? (lgB + cc * 2688 + u * 16)
                                        : (rmB + cc * 128 + (u - 168) * 16);
            CP16(dst + u * 16, src);
        }
        CP_COMMIT();
    }

    float f = 0.f, logc = 0.f;

    for (int c = 0; c < CRF_NC; c++) {
        if (c + 2 < CRF_NC) {
            const int nc = c + 2;
            const uint32_t dst = smem_u32(&sbuf[nc % 3][0]);
            for (int u = j; u < 176; u += 32) {
                const char* src = (u < 168) ? (lgB + nc * 2688 + u * 16)
                                            : (rmB + nc * 128 + (u - 168) * 16);
                CP16(dst + u * 16, src);
            }
            CP_COMMIT();
            asm volatile("cp.async.wait_group 2;" ::: "memory");
        } else if (c + 1 < CRF_NC) {
            asm volatile("cp.async.wait_group 1;" ::: "memory");
        } else {
            asm volatile("cp.async.wait_group 0;" ::: "memory");
        }
        __syncwarp();
        const float* sc = sbuf[c % 3];

        int w0 = 0;
        if (c == 0) {
            float a0 = (j < NLB) ? (start_t[j] + sc[j]) : -INFINITY;
            float m = a0;
            #pragma unroll
            for (int o = 16; o > 0; o >>= 1) m = fmaxf(m, __shfl_xor_sync(0xffffffffu, m, o));
            f = expf(a0 - m);
            logc = m;
            w0 = 1;
        }

        #pragma unroll 4
        for (int w = w0; w < CRF_CH; w++) {
            const int t = c * CRF_CH + w;
            const float e = (j < NLB) ? sc[w * NLB + j] : -1e30f;
            const float mt = sc[CRF_FB + w];
            float g0 = 0.f, g1 = 0.f, g2 = 0.f;
            #pragma unroll
            for (int i = 0; i < NLB; i += 3) {
                g0 = fmaf(__shfl_sync(0xffffffffu, f, i),     eT[i],     g0);
                g1 = fmaf(__shfl_sync(0xffffffffu, f, i + 1), eT[i + 1], g1);
                g2 = fmaf(__shfl_sync(0xffffffffu, f, i + 2), eT[i + 2], g2);
            }
            float fn = ((g0 + g1) + g2) * __expf(e - mt);
            logc += mt;
            if ((t & 7) == 7) {
                float mx = fn;
                #pragma unroll
                for (int o = 16; o > 0; o >>= 1) mx = fmaxf(mx, __shfl_xor_sync(0xffffffffu, mx, o));
                fn = fn / mx;
                logc += logf(mx);
            }
            f = fn;
        }
        __syncwarp();
    }

    float sf = (j < NLB) ? f * expf(end_t[j]) : 0.f;
    #pragma unroll
    for (int o = 16; o > 0; o >>= 1) sf += __shfl_xor_sync(0xffffffffu, sf, o);
    const float logZ = logc + logf(sf);

    float sc2 = 0.f;
    for (int t = j; t < LL; t += 32) {
        const int lt_ = lab[t];
        sc2 += lg[t * NLB + lt_];
        if (t >= 1) sc2 += trans[lab[t - 1] * NLB + lt_];
    }
    #pragma unroll
    for (int o = 16; o > 0; o >>= 1) sc2 += __shfl_xor_sync(0xffffffffu, sc2, o);
    if (j == 0) {
        sc2 += start_t[lab[0]] + end_t[lab[LL - 1]];
        g_nll[b] = logZ - sc2;
    }
}

// ---------------- K4: loss ----------------
__global__ void k4_loss(float* __restrict__ out_loss) {
    float v = g_nll[threadIdx.x];
    #pragma unroll
    for (int o = 16; o > 0; o >>= 1) v += __shfl_xor_sync(0xffffffffu, v, o);
    if (threadIdx.x == 0) *out_loss = v * (1.f / BB);
}

extern "C" void kernel_launch(void* const* d_in, const int* in_sizes, int n_in,
                              void* d_out, int out_size) {
    const float* seq    = (const float*)d_in[0];
    const int*   labels = (const int*)  d_in[1];
    const float* Wtok   = (const float*)d_in[3];
    const float* gamma  = (const float*)d_in[4];
    const float* beta   = (const float*)d_in[5];
    const float* ltab   = (const float*)d_in[6];
    const float* Wlab   = (const float*)d_in[7];
    const float* temp   = (const float*)d_in[8];
    const float* startt = (const float*)d_in[9];
    const float* endt   = (const float*)d_in[10];
    const float* trans  = (const float*)d_in[11];
    float* out = (float*)d_out;

    ksplitA<<<(int)(((size_t)MM * DIN / 4) / 256), 256>>>(seq);
    ksplitB<<<dim3(DIN / 32, HH / 32), dim3(32, 8)>>>(Wtok);
    k0_labelh<<<dim3(HH / 128, NLB), 128>>>(ltab, Wlab);

    const int smem1 = 2 * STAGE3;   // 81920
    cudaFuncSetAttribute(k1_mma, cudaFuncAttributeMaxDynamicSharedMemorySize, smem1);
    k1_mma<<<dim3(HH / 128, MM / 128), 256, smem1>>>();

    const int smem2 = NLB * HH * (int)sizeof(float);   // 86016
    cudaFuncSetAttribute(k2_fused, cudaFuncAttributeMaxDynamicSharedMemorySize, smem2);
    k2_fused<<<MM / 64, 256, smem2>>>(gamma, beta, temp, out);

    k3_crf<<<BB, 32>>>(out, labels, startt, endt, trans);
    k4_loss<<<1, 32>>>(out + (out_size - 1));
}

// round 11
// speedup vs baseline: 1.3156x; 1.3156x over previous
#include <cuda_runtime.h>
#include <cuda_bf16.h>
#include <math.h>
#include <stdint.h>

#define BB   32
#define LL   1024
#define DIN  2048
#define HH   1024
#define NLB  21
#define EE   768
#define MM   (BB*LL)
#define LN_EPS 1e-5f

// ---------------- device scratch ----------------
__device__ __align__(16) float g_h[(size_t)MM * HH];
__device__ __align__(16) float g_bt[(size_t)HH * DIN];   // W_tok transposed [n][k], tf32-rounded
__device__ __align__(16) float g_labelh[NLB * HH];
__device__ __align__(16) float g_rowmax[MM];
__device__ float g_nll[BB];

// ---------------- helpers ----------------
__device__ __forceinline__ uint32_t smem_u32(const void* p) {
    uint32_t a;
    asm("{ .reg .u64 t; cvta.to.shared.u64 t, %1; cvt.u32.u64 %0, t; }" : "=r"(a) : "l"(p));
    return a;
}
#define CP16(ds, sp) asm volatile("cp.async.cg.shared.global [%0], [%1], 16;" \
    :: "r"(ds), "l"(__cvta_generic_to_global(sp)) : "memory")
#define CP_COMMIT() asm volatile("cp.async.commit_group;" ::: "memory")
#define LDSM_X4(r0, r1, r2, r3, a) asm volatile( \
    "ldmatrix.sync.aligned.m8n8.x4.shared.b16 {%0,%1,%2,%3}, [%4];" \
    : "=r"(r0), "=r"(r1), "=r"(r2), "=r"(r3) : "r"(a))
#define CVT_TF32(x) asm("cvt.rna.tf32.f32 %0, %1;" : "=r"(x) : "f"(__uint_as_float(x)))
#define MMAT(d, a0, a1, a2, a3, b0, b1) asm volatile( \
    "mma.sync.aligned.m16n8k8.row.col.f32.tf32.tf32.f32 " \
    "{%0,%1,%2,%3}, {%4,%5,%6,%7}, {%8,%9}, {%0,%1,%2,%3};" \
    : "+f"((d)[0]), "+f"((d)[1]), "+f"((d)[2]), "+f"((d)[3]) \
    : "r"(a0), "r"(a1), "r"(a2), "r"(a3), "r"(b0), "r"(b1))

// ---------------- W transpose + tf32 round: g_bt[n][k] = rna(W[k][n]) ----------------
__global__ void ksplitBt(const float* __restrict__ W) {
    __shared__ float tile[32][33];
    const int kb = blockIdx.x * 32, nb = blockIdx.y * 32;
    const int tx = threadIdx.x, ty = threadIdx.y;  // 32 x 8
    #pragma unroll
    for (int i = 0; i < 32; i += 8)
        tile[ty + i][tx] = W[(size_t)(kb + ty + i) * HH + nb + tx];
    __syncthreads();
    #pragma unroll
    for (int i = 0; i < 32; i += 8) {
        float v = tile[tx][ty + i];   // W[kb+tx][nb+ty+i]
        uint32_t o;
        asm("cvt.rna.tf32.f32 %0, %1;" : "=r"(o) : "f"(v));
        g_bt[(size_t)(nb + ty + i) * DIN + kb + tx] = __uint_as_float(o);
    }
}

// ---------------- K0: label_h ----------------
__global__ void k0_labelh(const float* __restrict__ lt, const float* __restrict__ wl) {
    const int n = blockIdx.y;
    const int h = blockIdx.x * 128 + threadIdx.x;
    float acc = 0.f;
    const float* ltr = lt + n * EE;
    #pragma unroll 4
    for (int e = 0; e < EE; e++) acc = fmaf(ltr[e], wl[(size_t)e * HH + h], acc);
    g_labelh[n * HH + h] = acc;
}

// ---------------- K1: TF32 GEMM, 128x256 tile, 512 thr, KC=64, 2-stage ----------------
#define KC 64
#define NCH (DIN / KC)        // 32
#define TPB 272               // smem row pitch bytes (17*16B, conflict-free LDSM)
#define ASIZE (128 * TPB)     // 34816
#define BSIZE (256 * TPB)     // 69632
#define STAGE (ASIZE + BSIZE) // 104448

__device__ __forceinline__ void prefetch_t(uint32_t sbuf, const float* __restrict__ A,
                                           int cRow, int cCol, int k0, int tid) {
    #pragma unroll
    for (int q = 0; q < 12; q++) {
        const int id = q * 512 + tid;     // 0..6143
        const int seg = id & 15;
        if (id < 2048) {                  // A: 128 rows x 16 segs
            const int r = id >> 4;
            CP16(sbuf + (uint32_t)(r * TPB + seg * 16),
                 A + (size_t)(cRow + r) * DIN + k0 + seg * 4);
        } else {                          // B: 256 rows x 16 segs
            const int r = (id - 2048) >> 4;
            CP16(sbuf + (uint32_t)ASIZE + (uint32_t)(r * TPB + seg * 16),
                 g_bt + (size_t)(cCol + r) * DIN + k0 + seg * 4);
        }
    }
}

__global__ __launch_bounds__(512, 1) void k1_mma(const float* __restrict__ A) {
    extern __shared__ char sm[];
    const int tid = threadIdx.x, lane = tid & 31, wid = tid >> 5;
    const int cCol = blockIdx.x * 256, cRow = blockIdx.y * 128;
    const int wm = wid >> 2, wn = wid & 3;  // warp tile 32M x 64N
    const uint32_t sb = smem_u32(sm);

    float acc[2][8][4];
    #pragma unroll
    for (int i = 0; i < 2; i++)
        #pragma unroll
        for (int j = 0; j < 8; j++)
            #pragma unroll
            for (int k = 0; k < 4; k++) acc[i][j][k] = 0.f;

    prefetch_t(sb, A, cRow, cCol, 0, tid);
    CP_COMMIT();

    // ldmatrix per-lane address components (b16 reinterp of fp32 tiles)
    // A x4 tiles: [m0-7,k0-3][m8-15,k0-3][m0-7,k4-7][m8-15,k4-7]
    const int aRow0 = wm * 32 + ((lane >> 3) & 1) * 8 + (lane & 7);
    const uint32_t aKb = (uint32_t)((lane >> 4) * 16);
    // B x4 tiles (two n-tiles): [n0-7,k0-3][n0-7,k4-7][n8-15,k0-3][n8-15,k4-7]
    const int bRow0 = wn * 64 + (lane >> 4) * 8 + (lane & 7);
    const uint32_t bKb = (uint32_t)(((lane >> 3) & 1) * 16);

    for (int c = 0; c < NCH; c++) {
        if (c + 1 < NCH) {
            prefetch_t(sb + (uint32_t)(((c + 1) & 1) * STAGE), A, cRow, cCol,
                       (c + 1) * KC, tid);
            CP_COMMIT();
            asm volatile("cp.async.wait_group 1;" ::: "memory");
        } else {
            asm volatile("cp.async.wait_group 0;" ::: "memory");
        }
        __syncthreads();
        const uint32_t stA = sb + (uint32_t)((c & 1) * STAGE);
        const uint32_t stB = stA + (uint32_t)ASIZE;

        #pragma unroll
        for (int ks = 0; ks < 8; ks++) {
            uint32_t a[2][4];
            #pragma unroll
            for (int mt = 0; mt < 2; mt++) {
                const uint32_t ao = stA + (uint32_t)((aRow0 + mt * 16) * TPB) + aKb
                                  + (uint32_t)(ks * 32);
                LDSM_X4(a[mt][0], a[mt][1], a[mt][2], a[mt][3], ao);
                CVT_TF32(a[mt][0]); CVT_TF32(a[mt][1]);
                CVT_TF32(a[mt][2]); CVT_TF32(a[mt][3]);
            }
            #pragma unroll
            for (int pr = 0; pr < 4; pr++) {      // pair of n-tiles per ldmatrix
                const uint32_t bo = stB + (uint32_t)((bRow0 + pr * 16) * TPB) + bKb
                                  + (uint32_t)(ks * 32);
                uint32_t b0, b1, b2, b3;
                LDSM_X4(b0, b1, b2, b3, bo);
                #pragma unroll
                for (int mt = 0; mt < 2; mt++) {
                    MMAT(acc[mt][2*pr],   a[mt][0], a[mt][1], a[mt][2], a[mt][3], b0, b1);
                    MMAT(acc[mt][2*pr+1], a[mt][0], a[mt][1], a[mt][2], a[mt][3], b2, b3);
                }
            }
        }
        __syncthreads();
    }

    #pragma unroll
    for (int mt = 0; mt < 2; mt++)
        #pragma unroll
        for (int nt = 0; nt < 8; nt++) {
            const int row = cRow + wm * 32 + mt * 16 + (lane >> 2);
            const int col = cCol + wn * 64 + nt * 8 + (lane & 3) * 2;
            float2 v0 = make_float2(acc[mt][nt][0], acc[mt][nt][1]);
            float2 v1 = make_float2(acc[mt][nt][2], acc[mt][nt][3]);
            *(float2*)&g_h[(size_t)row * HH + col] = v0;
            *(float2*)&g_h[(size_t)(row + 8) * HH + col] = v1;
        }
}

// ---------------- K2: warp-per-row LN + exact GELU + logits + rowmax ----------------
__global__ __launch_bounds__(256)
void k2_fused(const float* __restrict__ gamma, const float* __restrict__ beta,
              const float* __restrict__ temp_p, float* __restrict__ logits) {
    extern __shared__ float slh[];   // NLB*HH floats
    const int tid = threadIdx.x, lane = tid & 31, wid = tid >> 5;

    const float4* lh4 = (const float4*)g_labelh;
    float4* slh4 = (float4*)slh;
    #pragma unroll
    for (int i = tid; i < NLB * HH / 4; i += 256) slh4[i] = lh4[i];
    const float tempv = *temp_p;
    const float4* gamma4 = (const float4*)gamma;
    const float4* beta4  = (const float4*)beta;
    __syncthreads();

    const int rowbase = blockIdx.x * 64 + wid * 8;
    for (int r = 0; r < 8; r++) {
        const int row = rowbase + r;
        const float4* hr4 = (const float4*)(g_h + (size_t)row * HH);
        float4 xv[8];
        #pragma unroll
        for (int q = 0; q < 8; q++) xv[q] = hr4[lane + 32 * q];

        float s = 0.f, ss = 0.f;
        #pragma unroll
        for (int q = 0; q < 8; q++) {
            s  += xv[q].x + xv[q].y + xv[q].z + xv[q].w;
            ss += xv[q].x*xv[q].x + xv[q].y*xv[q].y + xv[q].z*xv[q].z + xv[q].w*xv[q].w;
        }
        #pragma unroll
        for (int o = 16; o > 0; o >>= 1) {
            s  += __shfl_xor_sync(0xffffffffu, s, o);
            ss += __shfl_xor_sync(0xffffffffu, ss, o);
        }
        const float mean = s * (1.f / HH);
        const float rstd = rsqrtf(ss * (1.f / HH) - mean * mean + LN_EPS);

        float acc[NLB];
        #pragma unroll
        for (int l = 0; l < NLB; l++) acc[l] = 0.f;

        #pragma unroll
        for (int q = 0; q < 8; q++) {
            const float4 g4 = gamma4[lane + 32 * q];
            const float4 b4 = beta4[lane + 32 * q];
            float y0 = (xv[q].x - mean) * rstd * g4.x + b4.x;
            float y1 = (xv[q].y - mean) * rstd * g4.y + b4.y;
            float y2 = (xv[q].z - mean) * rstd * g4.z + b4.z;
            float y3 = (xv[q].w - mean) * rstd * g4.w + b4.w;
            const float t0 = 0.5f * y0 * (1.f + erff(y0 * 0.70710678118654752f));
            const float t1 = 0.5f * y1 * (1.f + erff(y1 * 0.70710678118654752f));
            const float t2 = 0.5f * y2 * (1.f + erff(y2 * 0.70710678118654752f));
            const float t3 = 0.5f * y3 * (1.f + erff(y3 * 0.70710678118654752f));
            #pragma unroll
            for (int l = 0; l < NLB; l++) {
                const float4 w4 = slh4[l * 256 + lane + 32 * q];
                acc[l] = fmaf(t0, w4.x, fmaf(t1, w4.y, fmaf(t2, w4.z, fmaf(t3, w4.w, acc[l]))));
            }
        }

        float out = 0.f;
        #pragma unroll
        for (int l = 0; l < NLB; l++) {
            float v = acc[l];
            #pragma unroll
            for (int o = 16; o > 0; o >>= 1) v += __shfl_xor_sync(0xffffffffu, v, o);
            if (lane == l) out = v * tempv;
        }
        if (lane < NLB) logits[(size_t)row * NLB + lane] = out;
        float mv = (lane < NLB) ? out : -INFINITY;
        #pragma unroll
        for (int o = 16; o > 0; o >>= 1) mv = fmaxf(mv, __shfl_xor_sync(0xffffffffu, mv, o));
        if (lane == 0) g_rowmax[row] = mv;
    }
}

// ---------------- K3: CRF forward, cp.async-staged, exp domain, renorm /8 ----------------
#define CRF_CH 32
#define CRF_NC (LL / CRF_CH)
#define CRF_FB (CRF_CH * NLB)
#define CRF_BF (CRF_FB + CRF_CH)

__global__ void k3_crf(const float* __restrict__ logits, const int* __restrict__ labels,
                       const float* __restrict__ start_t, const float* __restrict__ end_t,
                       const float* __restrict__ trans) {
    __shared__ __align__(16) float sbuf[3][CRF_BF];
    const int b = blockIdx.x;
    const int j = threadIdx.x;  // 32 lanes
    float eT[NLB];
    #pragma unroll
    for (int i = 0; i < NLB; i++) eT[i] = (j < NLB) ? expf(trans[i * NLB + j]) : 0.f;

    const float* lg = logits + (size_t)b * LL * NLB;
    const float* rm = g_rowmax + (size_t)b * LL;
    const int* lab = labels + (size_t)b * LL;

    const char* lgB = (const char*)lg;
    const char* rmB = (const char*)rm;

    #pragma unroll
    for (int cc = 0; cc < 2; cc++) {
        const uint32_t dst = smem_u32(&sbuf[cc][0]);
        for (int u = j; u < 176; u += 32) {
            const char* src = (u < 168) ? (lgB + cc * 2688 + u * 16)
                                        : (rmB + cc * 128 + (u - 168) * 16);
            CP16(dst + u * 16, src);
        }
        CP_COMMIT();
    }

    float f = 0.f, logc = 0.f;

    for (int c = 0; c < CRF_NC; c++) {
        if (c + 2 < CRF_NC) {
            const int nc = c + 2;
            const uint32_t dst = smem_u32(&sbuf[nc % 3][0]);
            for (int u = j; u < 176; u += 32) {
                const char* src = (u < 168) ? (lgB + nc * 2688 + u * 16)
                                            : (rmB + nc * 128 + (u - 168) * 16);
                CP16(dst + u * 16, src);
            }
            CP_COMMIT();
            asm volatile("cp.async.wait_group 2;" ::: "memory");
        } else if (c + 1 < CRF_NC) {
            asm volatile("cp.async.wait_group 1;" ::: "memory");
        } else {
            asm volatile("cp.async.wait_group 0;" ::: "memory");
        }
        __syncwarp();
        const float* sc = sbuf[c % 3];

        int w0 = 0;
        if (c == 0) {
            float a0 = (j < NLB) ? (start_t[j] + sc[j]) : -INFINITY;
            float m = a0;
            #pragma unroll
            for (int o = 16; o > 0; o >>= 1) m = fmaxf(m, __shfl_xor_sync(0xffffffffu, m, o));
            f = expf(a0 - m);
            logc = m;
            w0 = 1;
        }

        #pragma unroll 4
        for (int w = w0; w < CRF_CH; w++) {
            const int t = c * CRF_CH + w;
            const float e = (j < NLB) ? sc[w * NLB + j] : -1e30f;
            const float mt = sc[CRF_FB + w];
            float g0 = 0.f, g1 = 0.f, g2 = 0.f;
            #pragma unroll
            for (int i = 0; i < NLB; i += 3) {
                g0 = fmaf(__shfl_sync(0xffffffffu, f, i),     eT[i],     g0);
                g1 = fmaf(__shfl_sync(0xffffffffu, f, i + 1), eT[i + 1], g1);
                g2 = fmaf(__shfl_sync(0xffffffffu, f, i + 2), eT[i + 2], g2);
            }
            float fn = ((g0 + g1) + g2) * __expf(e - mt);
            logc += mt;
            if ((t & 7) == 7) {
                float mx = fn;
                #pragma unroll
                for (int o = 16; o > 0; o >>= 1) mx = fmaxf(mx, __shfl_xor_sync(0xffffffffu, mx, o));
                fn = fn / mx;
                logc += logf(mx);
            }
            f = fn;
        }
        __syncwarp();
    }

    float sf = (j < NLB) ? f * expf(end_t[j]) : 0.f;
    #pragma unroll
    for (int o = 16; o > 0; o >>= 1) sf += __shfl_xor_sync(0xffffffffu, sf, o);
    const float logZ = logc + logf(sf);

    float sc2 = 0.f;
    for (int t = j; t < LL; t += 32) {
        const int lt_ = lab[t];
        sc2 += lg[t * NLB + lt_];
        if (t >= 1) sc2 += trans[lab[t - 1] * NLB + lt_];
    }
    #pragma unroll
    for (int o = 16; o > 0; o >>= 1) sc2 += __shfl_xor_sync(0xffffffffu, sc2, o);
    if (j == 0) {
        sc2 += start_t[lab[0]] + end_t[lab[LL - 1]];
        g_nll[b] = logZ - sc2;
    }
}

// ---------------- K4: loss ----------------
__global__ void k4_loss(float* __restrict__ out_loss) {
    float v = g_nll[threadIdx.x];
    #pragma unroll
    for (int o = 16; o > 0; o >>= 1) v += __shfl_xor_sync(0xffffffffu, v, o);
    if (threadIdx.x == 0) *out_loss = v * (1.f / BB);
}

extern "C" void kernel_launch(void* const* d_in, const int* in_sizes, int n_in,
                              void* d_out, int out_size) {
    const float* seq    = (const float*)d_in[0];
    const int*   labels = (const int*)  d_in[1];
    const float* Wtok   = (const float*)d_in[3];
    const float* gamma  = (const float*)d_in[4];
    const float* beta   = (const float*)d_in[5];
    const float* ltab   = (const float*)d_in[6];
    const float* Wlab   = (const float*)d_in[7];
    const float* temp   = (const float*)d_in[8];
    const float* startt = (const float*)d_in[9];
    const float* endt   = (const float*)d_in[10];
    const float* trans  = (const float*)d_in[11];
    float* out = (float*)d_out;

    ksplitBt<<<dim3(DIN / 32, HH / 32), dim3(32, 8)>>>(Wtok);
    k0_labelh<<<dim3(HH / 128, NLB), 128>>>(ltab, Wlab);

    const int smem1 = 2 * STAGE;   // 208896
    cudaFuncSetAttribute(k1_mma, cudaFuncAttributeMaxDynamicSharedMemorySize, smem1);
    k1_mma<<<dim3(HH / 256, MM / 128), 512, smem1>>>(seq);

    const int smem2 = NLB * HH * (int)sizeof(float);   // 86016
    cudaFuncSetAttribute(k2_fused, cudaFuncAttributeMaxDynamicSharedMemorySize, smem2);
    k2_fused<<<MM / 64, 256, smem2>>>(gamma, beta, temp, out);

    k3_crf<<<BB, 32>>>(out, labels, startt, endt, trans);
    k4_loss<<<1, 32>>>(out + (out_size - 1));
}

// round 12
// speedup vs baseline: 1.8592x; 1.4131x over previous
#include <cuda_runtime.h>
#include <cuda_fp16.h>
#include <math.h>
#include <stdint.h>

#define BB   32
#define LL   1024
#define DIN  2048
#define HH   1024
#define NLB  21
#define EE   768
#define MM   (BB*LL)
#define LN_EPS 1e-5f

// ---------------- device scratch ----------------
__device__ __align__(16) float g_h[(size_t)MM * HH];
__device__ __align__(16) __half g_af16[(size_t)MM * DIN];
__device__ __align__(16) __half g_bf16[(size_t)HH * DIN];   // [n][k]
__device__ __align__(16) float g_labelh[NLB * HH];
__device__ __align__(16) float g_rowmax[MM];
__device__ float g_nll[BB];

// ---------------- helpers ----------------
__device__ __forceinline__ uint32_t smem_u32(const void* p) {
    uint32_t a;
    asm("{ .reg .u64 t; cvta.to.shared.u64 t, %1; cvt.u32.u64 %0, t; }" : "=r"(a) : "l"(p));
    return a;
}
#define CP16(ds, sp) asm volatile("cp.async.cg.shared.global [%0], [%1], 16;" \
    :: "r"(ds), "l"(__cvta_generic_to_global(sp)) : "memory")
#define CP_COMMIT() asm volatile("cp.async.commit_group;" ::: "memory")
#define LDSM_X4(r0, r1, r2, r3, a) asm volatile( \
    "ldmatrix.sync.aligned.m8n8.x4.shared.b16 {%0,%1,%2,%3}, [%4];" \
    : "=r"(r0), "=r"(r1), "=r"(r2), "=r"(r3) : "r"(a))
#define MMAH(d, a0, a1, a2, a3, b0, b1) asm volatile( \
    "mma.sync.aligned.m16n8k16.row.col.f32.f16.f16.f32 " \
    "{%0,%1,%2,%3}, {%4,%5,%6,%7}, {%8,%9}, {%0,%1,%2,%3};" \
    : "+f"((d)[0]), "+f"((d)[1]), "+f"((d)[2]), "+f"((d)[3]) \
    : "r"(a0), "r"(a1), "r"(a2), "r"(a3), "r"(b0), "r"(b1))

// ---------------- A convert: fp32 -> fp16 ----------------
__global__ void ksplitAh(const float* __restrict__ X) {
    const size_t i = ((size_t)blockIdx.x * blockDim.x + threadIdx.x) * 8;
    const float4 v0 = *(const float4*)(X + i);
    const float4 v1 = *(const float4*)(X + i + 4);
    __half2 h[4];
    h[0] = __floats2half2_rn(v0.x, v0.y);
    h[1] = __floats2half2_rn(v0.z, v0.w);
    h[2] = __floats2half2_rn(v1.x, v1.y);
    h[3] = __floats2half2_rn(v1.z, v1.w);
    *(uint4*)(g_af16 + i) = *(uint4*)h;
}

// ---------------- B transpose + convert: g_bf16[n][k] = fp16(W[k][n]) ----------------
__global__ void ksplitBh(const float* __restrict__ W) {
    __shared__ float tile[32][33];
    const int kb = blockIdx.x * 32, nb = blockIdx.y * 32;
    const int tx = threadIdx.x, ty = threadIdx.y;  // 32 x 8
    #pragma unroll
    for (int i = 0; i < 32; i += 8)
        tile[ty + i][tx] = W[(size_t)(kb + ty + i) * HH + nb + tx];
    __syncthreads();
    #pragma unroll
    for (int i = 0; i < 32; i += 8)
        g_bf16[(size_t)(nb + ty + i) * DIN + kb + tx] = __float2half(tile[tx][ty + i]);
}

// ---------------- K0: label_h ----------------
__global__ void k0_labelh(const float* __restrict__ lt, const float* __restrict__ wl) {
    const int n = blockIdx.y;
    const int h = blockIdx.x * 128 + threadIdx.x;
    float acc = 0.f;
    const float* ltr = lt + n * EE;
    #pragma unroll 4
    for (int e = 0; e < EE; e++) acc = fmaf(ltr[e], wl[(size_t)e * HH + h], acc);
    g_labelh[n * HH + h] = acc;
}

// ---------------- K1: fp16 GEMM, 128x256 tile, 512 thr, KC=64, 2-stage ----------------
#define KC 64
#define NCH (DIN / KC)        // 32
#define TP 144                // smem row pitch bytes (9*16B)
#define TILEA (128 * TP)      // 18432
#define TILEB (256 * TP)      // 36864
#define STAGE (TILEA + TILEB) // 55296

__device__ __forceinline__ void prefetch_h(uint32_t sbuf, int cRow, int cCol,
                                           int k0, int tid) {
    #pragma unroll
    for (int q = 0; q < 6; q++) {
        const int id = q * 512 + tid;      // 0..3071
        const int seg = id & 7;
        if (id < 1024) {                   // A: 128 rows x 8 segs
            const int r = id >> 3;
            CP16(sbuf + (uint32_t)(r * TP + seg * 16),
                 g_af16 + (size_t)(cRow + r) * DIN + k0 + seg * 8);
        } else {                           // B: 256 rows x 8 segs
            const int r = (id - 1024) >> 3;
            CP16(sbuf + (uint32_t)TILEA + (uint32_t)(r * TP + seg * 16),
                 g_bf16 + (size_t)(cCol + r) * DIN + k0 + seg * 8);
        }
    }
}

__global__ __launch_bounds__(512, 1) void k1_mma() {
    extern __shared__ char sm[];
    const int tid = threadIdx.x, lane = tid & 31, wid = tid >> 5;
    const int cCol = blockIdx.x * 256, cRow = blockIdx.y * 128;
    const int wm = wid >> 2, wn = wid & 3;  // warp tile 32M x 64N
    const uint32_t sb = smem_u32(sm);

    float acc[2][8][4];
    #pragma unroll
    for (int i = 0; i < 2; i++)
        #pragma unroll
        for (int j = 0; j < 8; j++)
            #pragma unroll
            for (int k = 0; k < 4; k++) acc[i][j][k] = 0.f;

    prefetch_h(sb, cRow, cCol, 0, tid);
    CP_COMMIT();

    const int aRow = wm * 32 + (lane & 15);            // + mt*16
    const uint32_t aKb = (uint32_t)((lane >> 4) * 16); // + ks*32
    const int bRow = wn * 64 + ((lane >> 4) & 1) * 8 + (lane & 7); // + p*16
    const uint32_t bKb = (uint32_t)(((lane >> 3) & 1) * 16);

    for (int c = 0; c < NCH; c++) {
        if (c + 1 < NCH) {
            prefetch_h(sb + (uint32_t)(((c + 1) & 1) * STAGE), cRow, cCol,
                       (c + 1) * KC, tid);
            CP_COMMIT();
            asm volatile("cp.async.wait_group 1;" ::: "memory");
        } else {
            asm volatile("cp.async.wait_group 0;" ::: "memory");
        }
        __syncthreads();
        const uint32_t stA = sb + (uint32_t)((c & 1) * STAGE);
        const uint32_t stB = stA + (uint32_t)TILEA;

        #pragma unroll
        for (int ks = 0; ks < 4; ks++) {
            uint32_t ah[2][4];
            #pragma unroll
            for (int mt = 0; mt < 2; mt++) {
                const uint32_t ao = stA + (uint32_t)((aRow + mt * 16) * TP) + aKb
                                  + (uint32_t)(ks * 32);
                LDSM_X4(ah[mt][0], ah[mt][1], ah[mt][2], ah[mt][3], ao);
            }
            #pragma unroll
            for (int p = 0; p < 4; p++) {
                const uint32_t bo = stB + (uint32_t)((bRow + p * 16) * TP) + bKb
                                  + (uint32_t)(ks * 32);
                uint32_t b0, b1, b2, b3;
                LDSM_X4(b0, b1, b2, b3, bo);
                #pragma unroll
                for (int mt = 0; mt < 2; mt++) {
                    MMAH(acc[mt][2*p],   ah[mt][0], ah[mt][1], ah[mt][2], ah[mt][3], b0, b1);
                    MMAH(acc[mt][2*p+1], ah[mt][0], ah[mt][1], ah[mt][2], ah[mt][3], b2, b3);
                }
            }
        }
        __syncthreads();
    }

    #pragma unroll
    for (int mt = 0; mt < 2; mt++)
        #pragma unroll
        for (int nt = 0; nt < 8; nt++) {
            const int row = cRow + wm * 32 + mt * 16 + (lane >> 2);
            const int col = cCol + wn * 64 + nt * 8 + (lane & 3) * 2;
            float2 v0 = make_float2(acc[mt][nt][0], acc[mt][nt][1]);
            float2 v1 = make_float2(acc[mt][nt][2], acc[mt][nt][3]);
            *(float2*)&g_h[(size_t)row * HH + col] = v0;
            *(float2*)&g_h[(size_t)(row + 8) * HH + col] = v1;
        }
}

// ---------------- K2: warp-per-row LN + exact GELU + logits + rowmax ----------------
__global__ __launch_bounds__(256)
void k2_fused(const float* __restrict__ gamma, const float* __restrict__ beta,
              const float* __restrict__ temp_p, float* __restrict__ logits) {
    extern __shared__ float slh[];   // NLB*HH floats
    const int tid = threadIdx.x, lane = tid & 31, wid = tid >> 5;

    const float4* lh4 = (const float4*)g_labelh;
    float4* slh4 = (float4*)slh;
    #pragma unroll
    for (int i = tid; i < NLB * HH / 4; i += 256) slh4[i] = lh4[i];
    const float tempv = *temp_p;
    const float4* gamma4 = (const float4*)gamma;
    const float4* beta4  = (const float4*)beta;
    __syncthreads();

    const int rowbase = blockIdx.x * 64 + wid * 8;
    for (int r = 0; r < 8; r++) {
        const int row = rowbase + r;
        const float4* hr4 = (const float4*)(g_h + (size_t)row * HH);
        float4 xv[8];
        #pragma unroll
        for (int q = 0; q < 8; q++) xv[q] = hr4[lane + 32 * q];

        float s = 0.f, ss = 0.f;
        #pragma unroll
        for (int q = 0; q < 8; q++) {
            s  += xv[q].x + xv[q].y + xv[q].z + xv[q].w;
            ss += xv[q].x*xv[q].x + xv[q].y*xv[q].y + xv[q].z*xv[q].z + xv[q].w*xv[q].w;
        }
        #pragma unroll
        for (int o = 16; o > 0; o >>= 1) {
            s  += __shfl_xor_sync(0xffffffffu, s, o);
            ss += __shfl_xor_sync(0xffffffffu, ss, o);
        }
        const float mean = s * (1.f / HH);
        const float rstd = rsqrtf(ss * (1.f / HH) - mean * mean + LN_EPS);

        float acc[NLB];
        #pragma unroll
        for (int l = 0; l < NLB; l++) acc[l] = 0.f;

        #pragma unroll
        for (int q = 0; q < 8; q++) {
            const float4 g4 = gamma4[lane + 32 * q];
            const float4 b4 = beta4[lane + 32 * q];
            float y0 = (xv[q].x - mean) * rstd * g4.x + b4.x;
            float y1 = (xv[q].y - mean) * rstd * g4.y + b4.y;
            float y2 = (xv[q].z - mean) * rstd * g4.z + b4.z;
            float y3 = (xv[q].w - mean) * rstd * g4.w + b4.w;
            const float t0 = 0.5f * y0 * (1.f + erff(y0 * 0.70710678118654752f));
            const float t1 = 0.5f * y1 * (1.f + erff(y1 * 0.70710678118654752f));
            const float t2 = 0.5f * y2 * (1.f + erff(y2 * 0.70710678118654752f));
            const float t3 = 0.5f * y3 * (1.f + erff(y3 * 0.70710678118654752f));
            #pragma unroll
            for (int l = 0; l < NLB; l++) {
                const float4 w4 = slh4[l * 256 + lane + 32 * q];
                acc[l] = fmaf(t0, w4.x, fmaf(t1, w4.y, fmaf(t2, w4.z, fmaf(t3, w4.w, acc[l]))));
            }
        }

        float out = 0.f;
        #pragma unroll
        for (int l = 0; l < NLB; l++) {
            float v = acc[l];
            #pragma unroll
            for (int o = 16; o > 0; o >>= 1) v += __shfl_xor_sync(0xffffffffu, v, o);
            if (lane == l) out = v * tempv;
        }
        if (lane < NLB) logits[(size_t)row * NLB + lane] = out;
        float mv = (lane < NLB) ? out : -INFINITY;
        #pragma unroll
        for (int o = 16; o > 0; o >>= 1) mv = fmaxf(mv, __shfl_xor_sync(0xffffffffu, mv, o));
        if (lane == 0) g_rowmax[row] = mv;
    }
}

// ---------------- K3: CRF forward, cp.async-staged, exp domain, renorm /8 ----------------
#define CRF_CH 32
#define CRF_NC (LL / CRF_CH)
#define CRF_FB (CRF_CH * NLB)
#define CRF_BF (CRF_FB + CRF_CH)

__global__ void k3_crf(const float* __restrict__ logits, const int* __restrict__ labels,
                       const float* __restrict__ start_t, const float* __restrict__ end_t,
                       const float* __restrict__ trans) {
    __shared__ __align__(16) float sbuf[3][CRF_BF];
    const int b = blockIdx.x;
    const int j = threadIdx.x;  // 32 lanes
    float eT[NLB];
    #pragma unroll
    for (int i = 0; i < NLB; i++) eT[i] = (j < NLB) ? expf(trans[i * NLB + j]) : 0.f;

    const float* lg = logits + (size_t)b * LL * NLB;
    const float* rm = g_rowmax + (size_t)b * LL;
    const int* lab = labels + (size_t)b * LL;

    const char* lgB = (const char*)lg;
    const char* rmB = (const char*)rm;

    #pragma unroll
    for (int cc = 0; cc < 2; cc++) {
        const uint32_t dst = smem_u32(&sbuf[cc][0]);
        for (int u = j; u < 176; u += 32) {
            const char* src = (u < 168) ? (lgB + cc * 2688 + u * 16)
                                        : (rmB + cc * 128 + (u - 168) * 16);
            CP16(dst + u * 16, src);
        }
        CP_COMMIT();
    }

    float f = 0.f, logc = 0.f;

    for (int c = 0; c < CRF_NC; c++) {
        if (c + 2 < CRF_NC) {
            const int nc = c + 2;
            const uint32_t dst = smem_u32(&sbuf[nc % 3][0]);
            for (int u = j; u < 176; u += 32) {
                const char* src = (u < 168) ? (lgB + nc * 2688 + u * 16)
                                            : (rmB + nc * 128 + (u - 168) * 16);
                CP16(dst + u * 16, src);
            }
            CP_COMMIT();
            asm volatile("cp.async.wait_group 2;" ::: "memory");
        } else if (c + 1 < CRF_NC) {
            asm volatile("cp.async.wait_group 1;" ::: "memory");
        } else {
            asm volatile("cp.async.wait_group 0;" ::: "memory");
        }
        __syncwarp();
        const float* sc = sbuf[c % 3];

        int w0 = 0;
        if (c == 0) {
            float a0 = (j < NLB) ? (start_t[j] + sc[j]) : -INFINITY;
            float m = a0;
            #pragma unroll
            for (int o = 16; o > 0; o >>= 1) m = fmaxf(m, __shfl_xor_sync(0xffffffffu, m, o));
            f = expf(a0 - m);
            logc = m;
            w0 = 1;
        }

        #pragma unroll 4
        for (int w = w0; w < CRF_CH; w++) {
            const int t = c * CRF_CH + w;
            const float e = (j < NLB) ? sc[w * NLB + j] : -1e30f;
            const float mt = sc[CRF_FB + w];
            float g0 = 0.f, g1 = 0.f, g2 = 0.f;
            #pragma unroll
            for (int i = 0; i < NLB; i += 3) {
                g0 = fmaf(__shfl_sync(0xffffffffu, f, i),     eT[i],     g0);
                g1 = fmaf(__shfl_sync(0xffffffffu, f, i + 1), eT[i + 1], g1);
                g2 = fmaf(__shfl_sync(0xffffffffu, f, i + 2), eT[i + 2], g2);
            }
            float fn = ((g0 + g1) + g2) * __expf(e - mt);
            logc += mt;
            if ((t & 7) == 7) {
                float mx = fn;
                #pragma unroll
                for (int o = 16; o > 0; o >>= 1) mx = fmaxf(mx, __shfl_xor_sync(0xffffffffu, mx, o));
                fn = fn / mx;
                logc += logf(mx);
            }
            f = fn;
        }
        __syncwarp();
    }

    float sf = (j < NLB) ? f * expf(end_t[j]) : 0.f;
    #pragma unroll
    for (int o = 16; o > 0; o >>= 1) sf += __shfl_xor_sync(0xffffffffu, sf, o);
    const float logZ = logc + logf(sf);

    float sc2 = 0.f;
    for (int t = j; t < LL; t += 32) {
        const int lt_ = lab[t];
        sc2 += lg[t * NLB + lt_];
        if (t >= 1) sc2 += trans[lab[t - 1] * NLB + lt_];
    }
    #pragma unroll
    for (int o = 16; o > 0; o >>= 1) sc2 += __shfl_xor_sync(0xffffffffu, sc2, o);
    if (j == 0) {
        sc2 += start_t[lab[0]] + end_t[lab[LL - 1]];
        g_nll[b] = logZ - sc2;
    }
}

// ---------------- K4: loss ----------------
__global__ void k4_loss(float* __restrict__ out_loss) {
    float v = g_nll[threadIdx.x];
    #pragma unroll
    for (int o = 16; o > 0; o >>= 1) v += __shfl_xor_sync(0xffffffffu, v, o);
    if (threadIdx.x == 0) *out_loss = v * (1.f / BB);
}

extern "C" void kernel_launch(void* const* d_in, const int* in_sizes, int n_in,
                              void* d_out, int out_size) {
    const float* seq    = (const float*)d_in[0];
    const int*   labels = (const int*)  d_in[1];
    const float* Wtok   = (const float*)d_in[3];
    const float* gamma  = (const float*)d_in[4];
    const float* beta   = (const float*)d_in[5];
    const float* ltab   = (const float*)d_in[6];
    const float* Wlab   = (const float*)d_in[7];
    const float* temp   = (const float*)d_in[8];
    const float* startt = (const float*)d_in[9];
    const float* endt   = (const float*)d_in[10];
    const float* trans  = (const float*)d_in[11];
    float* out = (float*)d_out;

    ksplitAh<<<(int)(((size_t)MM * DIN / 8) / 256), 256>>>(seq);
    ksplitBh<<<dim3(DIN / 32, HH / 32), dim3(32, 8)>>>(Wtok);
    k0_labelh<<<dim3(HH / 128, NLB), 128>>>(ltab, Wlab);

    const int smem1 = 2 * STAGE;   // 110592
    cudaFuncSetAttribute(k1_mma, cudaFuncAttributeMaxDynamicSharedMemorySize, smem1);
    k1_mma<<<dim3(HH / 256, MM / 128), 512, smem1>>>();

    const int smem2 = NLB * HH * (int)sizeof(float);   // 86016
    cudaFuncSetAttribute(k2_fused, cudaFuncAttributeMaxDynamicSharedMemorySize, smem2);
    k2_fused<<<MM / 64, 256, smem2>>>(gamma, beta, temp, out);

    k3_crf<<<BB, 32>>>(out, labels, startt, endt, trans);
    k4_loss<<<1, 32>>>(out + (out_size - 1));
}

// round 14
// speedup vs baseline: 1.9467x; 1.0471x over previous
#include <cuda_runtime.h>
#include <cuda_fp16.h>
#include <math.h>
#include <stdint.h>

#define BB   32
#define LL   1024
#define DIN  2048
#define HH   1024
#define NLB  21
#define EE   768
#define MM   (BB*LL)
#define LN_EPS 1e-5f

// ---------------- device scratch ----------------
__device__ __align__(16) float g_h[(size_t)MM * HH];
__device__ __align__(16) __half g_af16[(size_t)MM * DIN];
__device__ __align__(16) __half g_bf16[(size_t)HH * DIN];   // [n][k]
__device__ __align__(16) float g_labelh[NLB * HH];
__device__ __align__(16) float g_rowmax[MM];
__device__ float g_nll[BB];

// ---------------- helpers ----------------
__device__ __forceinline__ uint32_t smem_u32(const void* p) {
    uint32_t a;
    asm("{ .reg .u64 t; cvta.to.shared.u64 t, %1; cvt.u32.u64 %0, t; }" : "=r"(a) : "l"(p));
    return a;
}
#define CP16(ds, sp) asm volatile("cp.async.cg.shared.global [%0], [%1], 16;" \
    :: "r"(ds), "l"(__cvta_generic_to_global(sp)) : "memory")
#define CP_COMMIT() asm volatile("cp.async.commit_group;" ::: "memory")
#define LDSM_X4(r0, r1, r2, r3, a) asm volatile( \
    "ldmatrix.sync.aligned.m8n8.x4.shared.b16 {%0,%1,%2,%3}, [%4];" \
    : "=r"(r0), "=r"(r1), "=r"(r2), "=r"(r3) : "r"(a))
#define MMAH(d, a0, a1, a2, a3, b0, b1) asm volatile( \
    "mma.sync.aligned.m16n8k16.row.col.f32.f16.f16.f32 " \
    "{%0,%1,%2,%3}, {%4,%5,%6,%7}, {%8,%9}, {%0,%1,%2,%3};" \
    : "+f"((d)[0]), "+f"((d)[1]), "+f"((d)[2]), "+f"((d)[3]) \
    : "r"(a0), "r"(a1), "r"(a2), "r"(a3), "r"(b0), "r"(b1))

// ---------------- A convert: fp32 -> fp16 ----------------
__global__ void ksplitAh(const float* __restrict__ X) {
    const size_t i = ((size_t)blockIdx.x * blockDim.x + threadIdx.x) * 8;
    const float4 v0 = *(const float4*)(X + i);
    const float4 v1 = *(const float4*)(X + i + 4);
    __half2 h[4];
    h[0] = __floats2half2_rn(v0.x, v0.y);
    h[1] = __floats2half2_rn(v0.z, v0.w);
    h[2] = __floats2half2_rn(v1.x, v1.y);
    h[3] = __floats2half2_rn(v1.z, v1.w);
    *(uint4*)(g_af16 + i) = *(uint4*)h;
}

// ---------------- B transpose + convert: g_bf16[n][k] = fp16(W[k][n]) ----------------
__global__ void ksplitBh(const float* __restrict__ W) {
    __shared__ float tile[32][33];
    const int kb = blockIdx.x * 32, nb = blockIdx.y * 32;
    const int tx = threadIdx.x, ty = threadIdx.y;  // 32 x 8
    #pragma unroll
    for (int i = 0; i < 32; i += 8)
        tile[ty + i][tx] = W[(size_t)(kb + ty + i) * HH + nb + tx];
    __syncthreads();
    #pragma unroll
    for (int i = 0; i < 32; i += 8)
        g_bf16[(size_t)(nb + ty + i) * DIN + kb + tx] = __float2half(tile[tx][ty + i]);
}

// ---------------- K0: label_h ----------------
__global__ void k0_labelh(const float* __restrict__ lt, const float* __restrict__ wl) {
    const int n = blockIdx.y;
    const int h = blockIdx.x * 128 + threadIdx.x;
    float acc = 0.f;
    const float* ltr = lt + n * EE;
    #pragma unroll 4
    for (int e = 0; e < EE; e++) acc = fmaf(ltr[e], wl[(size_t)e * HH + h], acc);
    g_labelh[n * HH + h] = acc;
}

// ---------------- K1: fp16 GEMM, 128x256 tile, 512 thr, KC=64, interleaved prefetch ----------------
#define KC 64
#define NCH (DIN / KC)        // 32
#define TP 144                // smem row pitch bytes (9*16B)
#define TILEA (128 * TP)      // 18432
#define TILEB (256 * TP)      // 36864
#define STAGE (TILEA + TILEB) // 55296

// issue q-iterations [q0, q0+2) of the 6-iteration copy schedule
__device__ __forceinline__ void prefetch_pair(uint32_t sbuf, int cRow, int cCol,
                                              int k0, int tid, int q0) {
    #pragma unroll
    for (int qq = 0; qq < 2; qq++) {
        const int id = (q0 + qq) * 512 + tid;   // 0..3071
        const int seg = id & 7;
        if (id < 1024) {                   // A: 128 rows x 8 segs
            const int r = id >> 3;
            CP16(sbuf + (uint32_t)(r * TP + seg * 16),
                 g_af16 + (size_t)(cRow + r) * DIN + k0 + seg * 8);
        } else {                           // B: 256 rows x 8 segs
            const int r = (id - 1024) >> 3;
            CP16(sbuf + (uint32_t)TILEA + (uint32_t)(r * TP + seg * 16),
                 g_bf16 + (size_t)(cCol + r) * DIN + k0 + seg * 8);
        }
    }
}

__global__ __launch_bounds__(512, 1) void k1_mma() {
    extern __shared__ char sm[];
    const int tid = threadIdx.x, lane = tid & 31, wid = tid >> 5;
    const int cCol = blockIdx.x * 256, cRow = blockIdx.y * 128;
    const int wm = wid >> 2, wn = wid & 3;  // warp tile 32M x 64N
    const uint32_t sb = smem_u32(sm);

    float acc[2][8][4];
    #pragma unroll
    for (int i = 0; i < 2; i++)
        #pragma unroll
        for (int j = 0; j < 8; j++)
            #pragma unroll
            for (int k = 0; k < 4; k++) acc[i][j][k] = 0.f;

    prefetch_pair(sb, cRow, cCol, 0, tid, 0);
    prefetch_pair(sb, cRow, cCol, 0, tid, 2);
    prefetch_pair(sb, cRow, cCol, 0, tid, 4);
    CP_COMMIT();

    const int aRow = wm * 32 + (lane & 15);            // + mt*16
    const uint32_t aKb = (uint32_t)((lane >> 4) * 16); // + ks*32
    const int bRow = wn * 64 + ((lane >> 4) & 1) * 8 + (lane & 7); // + p*16
    const uint32_t bKb = (uint32_t)(((lane >> 3) & 1) * 16);

    for (int c = 0; c < NCH; c++) {
        asm volatile("cp.async.wait_group 0;" ::: "memory");
        __syncthreads();
        const uint32_t stA = sb + (uint32_t)((c & 1) * STAGE);
        const uint32_t stB = stA + (uint32_t)TILEA;
        const bool pf = (c + 1 < NCH);
        const uint32_t nbuf = sb + (uint32_t)(((c + 1) & 1) * STAGE);
        const int nk0 = (c + 1) * KC;

        #pragma unroll
        for (int ks = 0; ks < 4; ks++) {
            // spread next-chunk copy issue across the MMA work
            if (pf && ks < 3) prefetch_pair(nbuf, cRow, cCol, nk0, tid, ks * 2);

            uint32_t ah[2][4];
            #pragma unroll
            for (int mt = 0; mt < 2; mt++) {
                const uint32_t ao = stA + (uint32_t)((aRow + mt * 16) * TP) + aKb
                                  + (uint32_t)(ks * 32);
                LDSM_X4(ah[mt][0], ah[mt][1], ah[mt][2], ah[mt][3], ao);
            }
            #pragma unroll
            for (int p = 0; p < 4; p++) {
                const uint32_t bo = stB + (uint32_t)((bRow + p * 16) * TP) + bKb
                                  + (uint32_t)(ks * 32);
                uint32_t b0, b1, b2, b3;
                LDSM_X4(b0, b1, b2, b3, bo);
                #pragma unroll
                for (int mt = 0; mt < 2; mt++) {
                    MMAH(acc[mt][2*p],   ah[mt][0], ah[mt][1], ah[mt][2], ah[mt][3], b0, b1);
                    MMAH(acc[mt][2*p+1], ah[mt][0], ah[mt][1], ah[mt][2], ah[mt][3], b2, b3);
                }
            }
            if (pf && ks == 2) CP_COMMIT();
        }
    }

    #pragma unroll
    for (int mt = 0; mt < 2; mt++)
        #pragma unroll
        for (int nt = 0; nt < 8; nt++) {
            const int row = cRow + wm * 32 + mt * 16 + (lane >> 2);
            const int col = cCol + wn * 64 + nt * 8 + (lane & 3) * 2;
            float2 v0 = make_float2(acc[mt][nt][0], acc[mt][nt][1]);
            float2 v1 = make_float2(acc[mt][nt][2], acc[mt][nt][3]);
            *(float2*)&g_h[(size_t)row * HH + col] = v0;
            *(float2*)&g_h[(size_t)(row + 8) * HH + col] = v1;
        }
}

// ---------------- K2: warp-per-row LN + exact GELU + logits + rowmax (fp16 table) ----------------
__global__ __launch_bounds__(256)
void k2_fused(const float* __restrict__ gamma, const float* __restrict__ beta,
              const float* __restrict__ temp_p, float* __restrict__ logits) {
    extern __shared__ char smraw[];
    uint4* slh8 = (uint4*)smraw;           // NLB*HH halves as half8 chunks (NLB*128)
    const int tid = threadIdx.x, lane = tid & 31, wid = tid >> 5;

    // convert label table fp32 -> fp16 into smem
    const float4* lh4 = (const float4*)g_labelh;
    for (int i = tid; i < NLB * HH / 8; i += 256) {
        const float4 a = lh4[2 * i], b = lh4[2 * i + 1];
        __half2 h[4];
        h[0] = __floats2half2_rn(a.x, a.y);
        h[1] = __floats2half2_rn(a.z, a.w);
        h[2] = __floats2half2_rn(b.x, b.y);
        h[3] = __floats2half2_rn(b.z, b.w);
        slh8[i] = *(uint4*)h;
    }
    const float tempv = *temp_p;
    const float4* gamma4 = (const float4*)gamma;
    const float4* beta4  = (const float4*)beta;
    __syncthreads();

    const int rowbase = blockIdx.x * 64 + wid * 8;
    for (int r = 0; r < 8; r++) {
        const int row = rowbase + r;
        const float4* hr4 = (const float4*)(g_h + (size_t)row * HH);
        // lane owns elements [8*lane + 256*q4, +8) for q4 in 0..3
        float4 xv[8];
        #pragma unroll
        for (int q4 = 0; q4 < 4; q4++) {
            xv[2*q4]   = hr4[lane * 2 + 64 * q4];
            xv[2*q4+1] = hr4[lane * 2 + 64 * q4 + 1];
        }

        float s = 0.f, ss = 0.f;
        #pragma unroll
        for (int q = 0; q < 8; q++) {
            s  += xv[q].x + xv[q].y + xv[q].z + xv[q].w;
            ss += xv[q].x*xv[q].x + xv[q].y*xv[q].y + xv[q].z*xv[q].z + xv[q].w*xv[q].w;
        }
        #pragma unroll
        for (int o = 16; o > 0; o >>= 1) {
            s  += __shfl_xor_sync(0xffffffffu, s, o);
            ss += __shfl_xor_sync(0xffffffffu, ss, o);
        }
        const float mean = s * (1.f / HH);
        const float rstd = rsqrtf(ss * (1.f / HH) - mean * mean + LN_EPS);

        // GELU into t[32]  (gamma/beta index MATCHES xv: lane*2 + 64*(q>>1) + (q&1))
        float t[32];
        #pragma unroll
        for (int q = 0; q < 8; q++) {
            const int gi = lane * 2 + 64 * (q >> 1) + (q & 1);
            const float4 g4 = gamma4[gi];
            const float4 b4 = beta4[gi];
            float y0 = (xv[q].x - mean) * rstd * g4.x + b4.x;
            float y1 = (xv[q].y - mean) * rstd * g4.y + b4.y;
            float y2 = (xv[q].z - mean) * rstd * g4.z + b4.z;
            float y3 = (xv[q].w - mean) * rstd * g4.w + b4.w;
            t[q*4+0] = 0.5f * y0 * (1.f + erff(y0 * 0.70710678118654752f));
            t[q*4+1] = 0.5f * y1 * (1.f + erff(y1 * 0.70710678118654752f));
            t[q*4+2] = 0.5f * y2 * (1.f + erff(y2 * 0.70710678118654752f));
            t[q*4+3] = 0.5f * y3 * (1.f + erff(y3 * 0.70710678118654752f));
        }

        float acc[NLB];
        #pragma unroll
        for (int l = 0; l < NLB; l++) acc[l] = 0.f;

        #pragma unroll
        for (int q4 = 0; q4 < 4; q4++) {
            const float* tq = t + q4 * 8;
            #pragma unroll
            for (int l = 0; l < NLB; l++) {
                const uint4 w = slh8[l * 128 + lane + 32 * q4];
                const __half2* wh = (const __half2*)&w;
                const float2 f0 = __half22float2(wh[0]);
                const float2 f1 = __half22float2(wh[1]);
                const float2 f2 = __half22float2(wh[2]);
                const float2 f3 = __half22float2(wh[3]);
                float a0 = fmaf(tq[0], f0.x, tq[1] * f0.y);
                float a1 = fmaf(tq[2], f1.x, tq[3] * f1.y);
                float a2 = fmaf(tq[4], f2.x, tq[5] * f2.y);
                float a3 = fmaf(tq[6], f3.x, tq[7] * f3.y);
                acc[l] += (a0 + a1) + (a2 + a3);
            }
        }

        float out = 0.f;
        #pragma unroll
        for (int l = 0; l < NLB; l++) {
            float v = acc[l];
            #pragma unroll
            for (int o = 16; o > 0; o >>= 1) v += __shfl_xor_sync(0xffffffffu, v, o);
            if (lane == l) out = v * tempv;
        }
        if (lane < NLB) logits[(size_t)row * NLB + lane] = out;
        float mv = (lane < NLB) ? out : -INFINITY;
        #pragma unroll
        for (int o = 16; o > 0; o >>= 1) mv = fmaxf(mv, __shfl_xor_sync(0xffffffffu, mv, o));
        if (lane == 0) g_rowmax[row] = mv;
    }
}

// ---------------- K3: CRF forward, cp.async-staged, exp domain, renorm /8 ----------------
#define CRF_CH 32
#define CRF_NC (LL / CRF_CH)
#define CRF_FB (CRF_CH * NLB)
#define CRF_BF (CRF_FB + CRF_CH)

__global__ void k3_crf(const float* __restrict__ logits, const int* __restrict__ labels,
                       const float* __restrict__ start_t, const float* __restrict__ end_t,
                       const float* __restrict__ trans) {
    __shared__ __align__(16) float sbuf[3][CRF_BF];
    const int b = blockIdx.x;
    const int j = threadIdx.x;  // 32 lanes
    float eT[NLB];
    #pragma unroll
    for (int i = 0; i < NLB; i++) eT[i] = (j < NLB) ? expf(trans[i * NLB + j]) : 0.f;

    const float* lg = logits + (size_t)b * LL * NLB;
    const float* rm = g_rowmax + (size_t)b * LL;
    const int* lab = labels + (size_t)b * LL;

    const char* lgB = (const char*)lg;
    const char* rmB = (const char*)rm;

    #pragma unroll
    for (int cc = 0; cc < 2; cc++) {
        const uint32_t dst = smem_u32(&sbuf[cc][0]);
        for (int u = j; u < 176; u += 32) {
            const char* src = (u < 168) ? (lgB + cc * 2688 + u * 16)
                                        : (rmB + cc * 128 + (u - 168) * 16);
            CP16(dst + u * 16, src);
        }
        CP_COMMIT();
    }

    float f = 0.f, logc = 0.f;

    for (int c = 0; c < CRF_NC; c++) {
        if (c + 2 < CRF_NC) {
            const int nc = c + 2;
            const uint32_t dst = smem_u32(&sbuf[nc % 3][0]);
            for (int u = j; u < 176; u += 32) {
                const char* src = (u < 168) ? (lgB + nc * 2688 + u * 16)
                                            : (rmB + nc * 128 + (u - 168) * 16);
                CP16(dst + u * 16, src);
            }
            CP_COMMIT();
            asm volatile("cp.async.wait_group 2;" ::: "memory");
        } else if (c + 1 < CRF_NC) {
            asm volatile("cp.async.wait_group 1;" ::: "memory");
        } else {
            asm volatile("cp.async.wait_group 0;" ::: "memory");
        }
        __syncwarp();
        const float* sc = sbuf[c % 3];

        int w0 = 0;
        if (c == 0) {
            float a0 = (j < NLB) ? (start_t[j] + sc[j]) : -INFINITY;
            float m = a0;
            #pragma unroll
            for (int o = 16; o > 0; o >>= 1) m = fmaxf(m, __shfl_xor_sync(0xffffffffu, m, o));
            f = expf(a0 - m);
            logc = m;
            w0 = 1;
        }

        #pragma unroll 4
        for (int w = w0; w < CRF_CH; w++) {
            const int t = c * CRF_CH + w;
            const float e = (j < NLB) ? sc[w * NLB + j] : -1e30f;
            const float mt = sc[CRF_FB + w];
            float g0 = 0.f, g1 = 0.f, g2 = 0.f;
            #pragma unroll
            for (int i = 0; i < NLB; i += 3) {
                g0 = fmaf(__shfl_sync(0xffffffffu, f, i),     eT[i],     g0);
                g1 = fmaf(__shfl_sync(0xffffffffu, f, i + 1), eT[i + 1], g1);
                g2 = fmaf(__shfl_sync(0xffffffffu, f, i + 2), eT[i + 2], g2);
            }
            float fn = ((g0 + g1) + g2) * __expf(e - mt);
            logc += mt;
            if ((t & 7) == 7) {
                float mx = fn;
                #pragma unroll
                for (int o = 16; o > 0; o >>= 1) mx = fmaxf(mx, __shfl_xor_sync(0xffffffffu, mx, o));
                fn = fn / mx;
                logc += logf(mx);
            }
            f = fn;
        }
        __syncwarp();
    }

    float sf = (j < NLB) ? f * expf(end_t[j]) : 0.f;
    #pragma unroll
    for (int o = 16; o > 0; o >>= 1) sf += __shfl_xor_sync(0xffffffffu, sf, o);
    const float logZ = logc + logf(sf);

    float sc2 = 0.f;
    for (int t = j; t < LL; t += 32) {
        const int lt_ = lab[t];
        sc2 += lg[t * NLB + lt_];
        if (t >= 1) sc2 += trans[lab[t - 1] * NLB + lt_];
    }
    #pragma unroll
    for (int o = 16; o > 0; o >>= 1) sc2 += __shfl_xor_sync(0xffffffffu, sc2, o);
    if (j == 0) {
        sc2 += start_t[lab[0]] + end_t[lab[LL - 1]];
        g_nll[b] = logZ - sc2;
    }
}

// ---------------- K4: loss ----------------
__global__ void k4_loss(float* __restrict__ out_loss) {
    float v = g_nll[threadIdx.x];
    #pragma unroll
    for (int o = 16; o > 0; o >>= 1) v += __shfl_xor_sync(0xffffffffu, v, o);
    if (threadIdx.x == 0) *out_loss = v * (1.f / BB);
}

extern "C" void kernel_launch(void* const* d_in, const int* in_sizes, int n_in,
                              void* d_out, int out_size) {
    const float* seq    = (const float*)d_in[0];
    const int*   labels = (const int*)  d_in[1];
    const float* Wtok   = (const float*)d_in[3];
    const float* gamma  = (const float*)d_in[4];
    const float* beta   = (const float*)d_in[5];
    const float* ltab   = (const float*)d_in[6];
    const float* Wlab   = (const float*)d_in[7];
    const float* temp   = (const float*)d_in[8];
    const float* startt = (const float*)d_in[9];
    const float* endt   = (const float*)d_in[10];
    const float* trans  = (const float*)d_in[11];
    float* out = (float*)d_out;

    ksplitAh<<<(int)(((size_t)MM * DIN / 8) / 256), 256>>>(seq);
    ksplitBh<<<dim3(DIN / 32, HH / 32), dim3(32, 8)>>>(Wtok);
    k0_labelh<<<dim3(HH / 128, NLB), 128>>>(ltab, Wlab);

    const int smem1 = 2 * STAGE;   // 110592
    cudaFuncSetAttribute(k1_mma, cudaFuncAttributeMaxDynamicSharedMemorySize, smem1);
    k1_mma<<<dim3(HH / 256, MM / 128), 512, smem1>>>();

    const int smem2 = NLB * HH * (int)sizeof(__half);   // 43008
    cudaFuncSetAttribute(k2_fused, cudaFuncAttributeMaxDynamicSharedMemorySize, smem2);
    k2_fused<<<MM / 64, 256, smem2>>>(gamma, beta, temp, out);

    k3_crf<<<BB, 32>>>(out, labels, startt, endt, trans);
    k4_loss<<<1, 32>>>(out + (out_size - 1));
}

// round 15
// speedup vs baseline: 1.9773x; 1.0157x over previous
#include <cuda_runtime.h>
#include <cuda_fp16.h>
#include <math.h>
#include <stdint.h>

#define BB   32
#define LL   1024
#define DIN  2048
#define HH   1024
#define NLB  21
#define EE   768
#define MM   (BB*LL)
#define LN_EPS 1e-5f

// ---------------- device scratch ----------------
__device__ __align__(16) float g_h[(size_t)MM * HH];
__device__ __align__(16) __half g_af16[(size_t)MM * DIN];
__device__ __align__(16) __half g_bf16[(size_t)HH * DIN];   // [n][k]
__device__ __align__(16) float g_labelh[NLB * HH];
__device__ __align__(16) float g_rowmax[MM];
__device__ float g_nll[BB];

// ---------------- helpers ----------------
__device__ __forceinline__ uint32_t smem_u32(const void* p) {
    uint32_t a;
    asm("{ .reg .u64 t; cvta.to.shared.u64 t, %1; cvt.u32.u64 %0, t; }" : "=r"(a) : "l"(p));
    return a;
}
#define CP16(ds, sp) asm volatile("cp.async.cg.shared.global [%0], [%1], 16;" \
    :: "r"(ds), "l"(__cvta_generic_to_global(sp)) : "memory")
#define CP_COMMIT() asm volatile("cp.async.commit_group;" ::: "memory")
#define LDSM_X4(r0, r1, r2, r3, a) asm volatile( \
    "ldmatrix.sync.aligned.m8n8.x4.shared.b16 {%0,%1,%2,%3}, [%4];" \
    : "=r"(r0), "=r"(r1), "=r"(r2), "=r"(r3) : "r"(a))
#define MMAH(d, a0, a1, a2, a3, b0, b1) asm volatile( \
    "mma.sync.aligned.m16n8k16.row.col.f32.f16.f16.f32 " \
    "{%0,%1,%2,%3}, {%4,%5,%6,%7}, {%8,%9}, {%0,%1,%2,%3};" \
    : "+f"((d)[0]), "+f"((d)[1]), "+f"((d)[2]), "+f"((d)[3]) \
    : "r"(a0), "r"(a1), "r"(a2), "r"(a3), "r"(b0), "r"(b1))

// ---------------- A convert: fp32 -> fp16 ----------------
__global__ void ksplitAh(const float* __restrict__ X) {
    const size_t i = ((size_t)blockIdx.x * blockDim.x + threadIdx.x) * 8;
    const float4 v0 = *(const float4*)(X + i);
    const float4 v1 = *(const float4*)(X + i + 4);
    __half2 h[4];
    h[0] = __floats2half2_rn(v0.x, v0.y);
    h[1] = __floats2half2_rn(v0.z, v0.w);
    h[2] = __floats2half2_rn(v1.x, v1.y);
    h[3] = __floats2half2_rn(v1.z, v1.w);
    *(uint4*)(g_af16 + i) = *(uint4*)h;
}

// ---------------- B transpose + convert: g_bf16[n][k] = fp16(W[k][n]) ----------------
__global__ void ksplitBh(const float* __restrict__ W) {
    __shared__ float tile[32][33];
    const int kb = blockIdx.x * 32, nb = blockIdx.y * 32;
    const int tx = threadIdx.x, ty = threadIdx.y;  // 32 x 8
    #pragma unroll
    for (int i = 0; i < 32; i += 8)
        tile[ty + i][tx] = W[(size_t)(kb + ty + i) * HH + nb + tx];
    __syncthreads();
    #pragma unroll
    for (int i = 0; i < 32; i += 8)
        g_bf16[(size_t)(nb + ty + i) * DIN + kb + tx] = __float2half(tile[tx][ty + i]);
}

// ---------------- K0: label_h ----------------
__global__ void k0_labelh(const float* __restrict__ lt, const float* __restrict__ wl) {
    const int n = blockIdx.y;
    const int h = blockIdx.x * 128 + threadIdx.x;
    float acc = 0.f;
    const float* ltr = lt + n * EE;
    #pragma unroll 4
    for (int e = 0; e < EE; e++) acc = fmaf(ltr[e], wl[(size_t)e * HH + h], acc);
    g_labelh[n * HH + h] = acc;
}

// ---------------- K1: fp16 GEMM, 128x256 tile, 512 thr, KC=64, 3-stage ----------------
#define KC 64
#define NCH (DIN / KC)        // 32
#define TP 144                // smem row pitch bytes (9*16B)
#define TILEA (128 * TP)      // 18432
#define TILEB (256 * TP)      // 36864
#define STAGE (TILEA + TILEB) // 55296
#define NST 3

// issue q-iterations [q0, q0+2) of the 6-iteration copy schedule
__device__ __forceinline__ void prefetch_pair(uint32_t sbuf, int cRow, int cCol,
                                              int k0, int tid, int q0) {
    #pragma unroll
    for (int qq = 0; qq < 2; qq++) {
        const int id = (q0 + qq) * 512 + tid;   // 0..3071
        const int seg = id & 7;
        if (id < 1024) {                   // A: 128 rows x 8 segs
            const int r = id >> 3;
            CP16(sbuf + (uint32_t)(r * TP + seg * 16),
                 g_af16 + (size_t)(cRow + r) * DIN + k0 + seg * 8);
        } else {                           // B: 256 rows x 8 segs
            const int r = (id - 1024) >> 3;
            CP16(sbuf + (uint32_t)TILEA + (uint32_t)(r * TP + seg * 16),
                 g_bf16 + (size_t)(cCol + r) * DIN + k0 + seg * 8);
        }
    }
}

__global__ __launch_bounds__(512, 1) void k1_mma() {
    extern __shared__ char sm[];
    const int tid = threadIdx.x, lane = tid & 31, wid = tid >> 5;
    const int cCol = blockIdx.x * 256, cRow = blockIdx.y * 128;
    const int wm = wid >> 2, wn = wid & 3;  // warp tile 32M x 64N
    const uint32_t sb = smem_u32(sm);

    float acc[2][8][4];
    #pragma unroll
    for (int i = 0; i < 2; i++)
        #pragma unroll
        for (int j = 0; j < 8; j++)
            #pragma unroll
            for (int k = 0; k < 4; k++) acc[i][j][k] = 0.f;

    // prologue: stage chunks 0 and 1 as separate groups
    prefetch_pair(sb, cRow, cCol, 0, tid, 0);
    prefetch_pair(sb, cRow, cCol, 0, tid, 2);
    prefetch_pair(sb, cRow, cCol, 0, tid, 4);
    CP_COMMIT();
    prefetch_pair(sb + STAGE, cRow, cCol, KC, tid, 0);
    prefetch_pair(sb + STAGE, cRow, cCol, KC, tid, 2);
    prefetch_pair(sb + STAGE, cRow, cCol, KC, tid, 4);
    CP_COMMIT();

    const int aRow = wm * 32 + (lane & 15);            // + mt*16
    const uint32_t aKb = (uint32_t)((lane >> 4) * 16); // + ks*32
    const int bRow = wn * 64 + ((lane >> 4) & 1) * 8 + (lane & 7); // + p*16
    const uint32_t bKb = (uint32_t)(((lane >> 3) & 1) * 16);

    int stage = 0;
    for (int c = 0; c < NCH; c++) {
        if (c + 1 < NCH) {
            asm volatile("cp.async.wait_group 1;" ::: "memory");
        } else {
            asm volatile("cp.async.wait_group 0;" ::: "memory");
        }
        __syncthreads();
        const uint32_t stA = sb + (uint32_t)(stage * STAGE);
        const uint32_t stB = stA + (uint32_t)TILEA;
        const bool pf = (c + 2 < NCH);
        int ps = stage + 2; if (ps >= NST) ps -= NST;
        const uint32_t nbuf = sb + (uint32_t)(ps * STAGE);
        const int nk0 = (c + 2) * KC;

        #pragma unroll
        for (int ks = 0; ks < 4; ks++) {
            // spread chunk c+2 copy issue across the MMA work
            if (pf && ks < 3) prefetch_pair(nbuf, cRow, cCol, nk0, tid, ks * 2);

            uint32_t ah[2][4];
            #pragma unroll
            for (int mt = 0; mt < 2; mt++) {
                const uint32_t ao = stA + (uint32_t)((aRow + mt * 16) * TP) + aKb
                                  + (uint32_t)(ks * 32);
                LDSM_X4(ah[mt][0], ah[mt][1], ah[mt][2], ah[mt][3], ao);
            }
            #pragma unroll
            for (int p = 0; p < 4; p++) {
                const uint32_t bo = stB + (uint32_t)((bRow + p * 16) * TP) + bKb
                                  + (uint32_t)(ks * 32);
                uint32_t b0, b1, b2, b3;
                LDSM_X4(b0, b1, b2, b3, bo);
                #pragma unroll
                for (int mt = 0; mt < 2; mt++) {
                    MMAH(acc[mt][2*p],   ah[mt][0], ah[mt][1], ah[mt][2], ah[mt][3], b0, b1);
                    MMAH(acc[mt][2*p+1], ah[mt][0], ah[mt][1], ah[mt][2], ah[mt][3], b2, b3);
                }
            }
            if (pf && ks == 2) CP_COMMIT();
        }
        stage = (stage + 1 == NST) ? 0 : stage + 1;
    }

    #pragma unroll
    for (int mt = 0; mt < 2; mt++)
        #pragma unroll
        for (int nt = 0; nt < 8; nt++) {
            const int row = cRow + wm * 32 + mt * 16 + (lane >> 2);
            const int col = cCol + wn * 64 + nt * 8 + (lane & 3) * 2;
            float2 v0 = make_float2(acc[mt][nt][0], acc[mt][nt][1]);
            float2 v1 = make_float2(acc[mt][nt][2], acc[mt][nt][3]);
            *(float2*)&g_h[(size_t)row * HH + col] = v0;
            *(float2*)&g_h[(size_t)(row + 8) * HH + col] = v1;
        }
}

// ---------------- K2: warp-per-row LN + exact GELU + logits + rowmax (fp16 table) ----------------
__global__ __launch_bounds__(256)
void k2_fused(const float* __restrict__ gamma, const float* __restrict__ beta,
              const float* __restrict__ temp_p, float* __restrict__ logits) {
    extern __shared__ char smraw[];
    uint4* slh8 = (uint4*)smraw;           // NLB*HH halves as half8 chunks (NLB*128)
    const int tid = threadIdx.x, lane = tid & 31, wid = tid >> 5;

    // convert label table fp32 -> fp16 into smem
    const float4* lh4 = (const float4*)g_labelh;
    for (int i = tid; i < NLB * HH / 8; i += 256) {
        const float4 a = lh4[2 * i], b = lh4[2 * i + 1];
        __half2 h[4];
        h[0] = __floats2half2_rn(a.x, a.y);
        h[1] = __floats2half2_rn(a.z, a.w);
        h[2] = __floats2half2_rn(b.x, b.y);
        h[3] = __floats2half2_rn(b.z, b.w);
        slh8[i] = *(uint4*)h;
    }
    const float tempv = *temp_p;
    const float4* gamma4 = (const float4*)gamma;
    const float4* beta4  = (const float4*)beta;
    __syncthreads();

    const int rowbase = blockIdx.x * 64 + wid * 8;
    for (int r = 0; r < 8; r++) {
        const int row = rowbase + r;
        const float4* hr4 = (const float4*)(g_h + (size_t)row * HH);
        // lane owns elements [8*lane + 256*q4, +8) for q4 in 0..3
        float4 xv[8];
        #pragma unroll
        for (int q4 = 0; q4 < 4; q4++) {
            xv[2*q4]   = hr4[lane * 2 + 64 * q4];
            xv[2*q4+1] = hr4[lane * 2 + 64 * q4 + 1];
        }

        float s = 0.f, ss = 0.f;
        #pragma unroll
        for (int q = 0; q < 8; q++) {
            s  += xv[q].x + xv[q].y + xv[q].z + xv[q].w;
            ss += xv[q].x*xv[q].x + xv[q].y*xv[q].y + xv[q].z*xv[q].z + xv[q].w*xv[q].w;
        }
        #pragma unroll
        for (int o = 16; o > 0; o >>= 1) {
            s  += __shfl_xor_sync(0xffffffffu, s, o);
            ss += __shfl_xor_sync(0xffffffffu, ss, o);
        }
        const float mean = s * (1.f / HH);
        const float rstd = rsqrtf(ss * (1.f / HH) - mean * mean + LN_EPS);

        // GELU into t[32]  (gamma/beta index MATCHES xv: lane*2 + 64*(q>>1) + (q&1))
        float t[32];
        #pragma unroll
        for (int q = 0; q < 8; q++) {
            const int gi = lane * 2 + 64 * (q >> 1) + (q & 1);
            const float4 g4 = gamma4[gi];
            const float4 b4 = beta4[gi];
            float y0 = (xv[q].x - mean) * rstd * g4.x + b4.x;
            float y1 = (xv[q].y - mean) * rstd * g4.y + b4.y;
            float y2 = (xv[q].z - mean) * rstd * g4.z + b4.z;
            float y3 = (xv[q].w - mean) * rstd * g4.w + b4.w;
            t[q*4+0] = 0.5f * y0 * (1.f + erff(y0 * 0.70710678118654752f));
            t[q*4+1] = 0.5f * y1 * (1.f + erff(y1 * 0.70710678118654752f));
            t[q*4+2] = 0.5f * y2 * (1.f + erff(y2 * 0.70710678118654752f));
            t[q*4+3] = 0.5f * y3 * (1.f + erff(y3 * 0.70710678118654752f));
        }

        float acc[NLB];
        #pragma unroll
        for (int l = 0; l < NLB; l++) acc[l] = 0.f;

        #pragma unroll
        for (int q4 = 0; q4 < 4; q4++) {
            const float* tq = t + q4 * 8;
            #pragma unroll
            for (int l = 0; l < NLB; l++) {
                const uint4 w = slh8[l * 128 + lane + 32 * q4];
                const __half2* wh = (const __half2*)&w;
                const float2 f0 = __half22float2(wh[0]);
                const float2 f1 = __half22float2(wh[1]);
                const float2 f2 = __half22float2(wh[2]);
                const float2 f3 = __half22float2(wh[3]);
                float a0 = fmaf(tq[0], f0.x, tq[1] * f0.y);
                float a1 = fmaf(tq[2], f1.x, tq[3] * f1.y);
                float a2 = fmaf(tq[4], f2.x, tq[5] * f2.y);
                float a3 = fmaf(tq[6], f3.x, tq[7] * f3.y);
                acc[l] += (a0 + a1) + (a2 + a3);
            }
        }

        float out = 0.f;
        #pragma unroll
        for (int l = 0; l < NLB; l++) {
            float v = acc[l];
            #pragma unroll
            for (int o = 16; o > 0; o >>= 1) v += __shfl_xor_sync(0xffffffffu, v, o);
            if (lane == l) out = v * tempv;
        }
        if (lane < NLB) logits[(size_t)row * NLB + lane] = out;
        float mv = (lane < NLB) ? out : -INFINITY;
        #pragma unroll
        for (int o = 16; o > 0; o >>= 1) mv = fmaxf(mv, __shfl_xor_sync(0xffffffffu, mv, o));
        if (lane == 0) g_rowmax[row] = mv;
    }
}

// ---------------- K3: CRF forward, cp.async-staged, exp domain, renorm /8 ----------------
#define CRF_CH 32
#define CRF_NC (LL / CRF_CH)
#define CRF_FB (CRF_CH * NLB)
#define CRF_BF (CRF_FB + CRF_CH)

__global__ void k3_crf(const float* __restrict__ logits, const int* __restrict__ labels,
                       const float* __restrict__ start_t, const float* __restrict__ end_t,
                       const float* __restrict__ trans) {
    __shared__ __align__(16) float sbuf[3][CRF_BF];
    const int b = blockIdx.x;
    const int j = threadIdx.x;  // 32 lanes
    float eT[NLB];
    #pragma unroll
    for (int i = 0; i < NLB; i++) eT[i] = (j < NLB) ? expf(trans[i * NLB + j]) : 0.f;

    const float* lg = logits + (size_t)b * LL * NLB;
    const float* rm = g_rowmax + (size_t)b * LL;
    const int* lab = labels + (size_t)b * LL;

    const char* lgB = (const char*)lg;
    const char* rmB = (const char*)rm;

    #pragma unroll
    for (int cc = 0; cc < 2; cc++) {
        const uint32_t dst = smem_u32(&sbuf[cc][0]);
        for (int u = j; u < 176; u += 32) {
            const char* src = (u < 168) ? (lgB + cc * 2688 + u * 16)
                                        : (rmB + cc * 128 + (u - 168) * 16);
            CP16(dst + u * 16, src);
        }
        CP_COMMIT();
    }

    float f = 0.f, logc = 0.f;

    for (int c = 0; c < CRF_NC; c++) {
        if (c + 2 < CRF_NC) {
            const int nc = c + 2;
            const uint32_t dst = smem_u32(&sbuf[nc % 3][0]);
            for (int u = j; u < 176; u += 32) {
                const char* src = (u < 168) ? (lgB + nc * 2688 + u * 16)
                                            : (rmB + nc * 128 + (u - 168) * 16);
                CP16(dst + u * 16, src);
            }
            CP_COMMIT();
            asm volatile("cp.async.wait_group 2;" ::: "memory");
        } else if (c + 1 < CRF_NC) {
            asm volatile("cp.async.wait_group 1;" ::: "memory");
        } else {
            asm volatile("cp.async.wait_group 0;" ::: "memory");
        }
        __syncwarp();
        const float* sc = sbuf[c % 3];

        int w0 = 0;
        if (c == 0) {
            float a0 = (j < NLB) ? (start_t[j] + sc[j]) : -INFINITY;
            float m = a0;
            #pragma unroll
            for (int o = 16; o > 0; o >>= 1) m = fmaxf(m, __shfl_xor_sync(0xffffffffu, m, o));
            f = expf(a0 - m);
            logc = m;
            w0 = 1;
        }

        #pragma unroll 4
        for (int w = w0; w < CRF_CH; w++) {
            const int t = c * CRF_CH + w;
            const float e = (j < NLB) ? sc[w * NLB + j] : -1e30f;
            const float mt = sc[CRF_FB + w];
            float g0 = 0.f, g1 = 0.f, g2 = 0.f;
            #pragma unroll
            for (int i = 0; i < NLB; i += 3) {
                g0 = fmaf(__shfl_sync(0xffffffffu, f, i),     eT[i],     g0);
                g1 = fmaf(__shfl_sync(0xffffffffu, f, i + 1), eT[i + 1], g1);
                g2 = fmaf(__shfl_sync(0xffffffffu, f, i + 2), eT[i + 2], g2);
            }
            float fn = ((g0 + g1) + g2) * __expf(e - mt);
            logc += mt;
            if ((t & 7) == 7) {
                float mx = fn;
                #pragma unroll
                for (int o = 16; o > 0; o >>= 1) mx = fmaxf(mx, __shfl_xor_sync(0xffffffffu, mx, o));
                fn = fn / mx;
                logc += logf(mx);
            }
            f = fn;
        }
        __syncwarp();
    }

    float sf = (j < NLB) ? f * expf(end_t[j]) : 0.f;
    #pragma unroll
    for (int o = 16; o > 0; o >>= 1) sf += __shfl_xor_sync(0xffffffffu, sf, o);
    const float logZ = logc + logf(sf);

    float sc2 = 0.f;
    for (int t = j; t < LL; t += 32) {
        const int lt_ = lab[t];
        sc2 += lg[t * NLB + lt_];
        if (t >= 1) sc2 += trans[lab[t - 1] * NLB + lt_];
    }
    #pragma unroll
    for (int o = 16; o > 0; o >>= 1) sc2 += __shfl_xor_sync(0xffffffffu, sc2, o);
    if (j == 0) {
        sc2 += start_t[lab[0]] + end_t[lab[LL - 1]];
        g_nll[b] = logZ - sc2;
    }
}

// ---------------- K4: loss ----------------
__global__ void k4_loss(float* __restrict__ out_loss) {
    float v = g_nll[threadIdx.x];
    #pragma unroll
    for (int o = 16; o > 0; o >>= 1) v += __shfl_xor_sync(0xffffffffu, v, o);
    if (threadIdx.x == 0) *out_loss = v * (1.f / BB);
}

extern "C" void kernel_launch(void* const* d_in, const int* in_sizes, int n_in,
                              void* d_out, int out_size) {
    const float* seq    = (const float*)d_in[0];
    const int*   labels = (const int*)  d_in[1];
    const float* Wtok   = (const float*)d_in[3];
    const float* gamma  = (const float*)d_in[4];
    const float* beta   = (const float*)d_in[5];
    const float* ltab   = (const float*)d_in[6];
    const float* Wlab   = (const float*)d_in[7];
    const float* temp   = (const float*)d_in[8];
    const float* startt = (const float*)d_in[9];
    const float* endt   = (const float*)d_in[10];
    const float* trans  = (const float*)d_in[11];
    float* out = (float*)d_out;

    ksplitAh<<<(int)(((size_t)MM * DIN / 8) / 256), 256>>>(seq);
    ksplitBh<<<dim3(DIN / 32, HH / 32), dim3(32, 8)>>>(Wtok);
    k0_labelh<<<dim3(HH / 128, NLB), 128>>>(ltab, Wlab);

    const int smem1 = NST * STAGE;   // 165888
    cudaFuncSetAttribute(k1_mma, cudaFuncAttributeMaxDynamicSharedMemorySize, smem1);
    k1_mma<<<dim3(HH / 256, MM / 128), 512, smem1>>>();

    const int smem2 = NLB * HH * (int)sizeof(__half);   // 43008
    cudaFuncSetAttribute(k2_fused, cudaFuncAttributeMaxDynamicSharedMemorySize, smem2);
    k2_fused<<<MM / 64, 256, smem2>>>(gamma, beta, temp, out);

    k3_crf<<<BB, 32>>>(out, labels, startt, endt, trans);
    k4_loss<<<1, 32>>>(out + (out_size - 1));
}

// round 16
// speedup vs baseline: 2.1521x; 1.0884x over previous
#include <cuda_runtime.h>
#include <cuda_fp16.h>
#include <math.h>
#include <stdint.h>

#define BB   32
#define LL   1024
#define DIN  2048
#define HH   1024
#define NLB  21
#define EE   768
#define MM   (BB*LL)
#define LN_EPS 1e-5f

// ---------------- device scratch ----------------
__device__ __align__(16) float g_h[(size_t)MM * HH];
__device__ __align__(16) __half g_af16[(size_t)MM * DIN];
__device__ __align__(16) __half g_bf16[(size_t)HH * DIN];   // [n][k]
__device__ __align__(16) float g_labelh[NLB * HH];
__device__ __align__(16) float g_rowmax[MM];
__device__ float g_nll[BB];

// ---------------- helpers ----------------
__device__ __forceinline__ uint32_t smem_u32(const void* p) {
    uint32_t a;
    asm("{ .reg .u64 t; cvta.to.shared.u64 t, %1; cvt.u32.u64 %0, t; }" : "=r"(a) : "l"(p));
    return a;
}
#define CP16(ds, sp) asm volatile("cp.async.cg.shared.global [%0], [%1], 16;" \
    :: "r"(ds), "l"(__cvta_generic_to_global(sp)) : "memory")
#define CP_COMMIT() asm volatile("cp.async.commit_group;" ::: "memory")
#define LDSM_X4(r0, r1, r2, r3, a) asm volatile( \
    "ldmatrix.sync.aligned.m8n8.x4.shared.b16 {%0,%1,%2,%3}, [%4];" \
    : "=r"(r0), "=r"(r1), "=r"(r2), "=r"(r3) : "r"(a))
#define MMAH(d, a0, a1, a2, a3, b0, b1) asm volatile( \
    "mma.sync.aligned.m16n8k16.row.col.f32.f16.f16.f32 " \
    "{%0,%1,%2,%3}, {%4,%5,%6,%7}, {%8,%9}, {%0,%1,%2,%3};" \
    : "+f"((d)[0]), "+f"((d)[1]), "+f"((d)[2]), "+f"((d)[3]) \
    : "r"(a0), "r"(a1), "r"(a2), "r"(a3), "r"(b0), "r"(b1))

// ---------------- Kpro: fused prologue ----------------
// blocks [0, 84):            label_h (k0), 4-acc ILP
// blocks [84, 84+2048):      B transpose + fp16 convert
// blocks [2132, 2132+32768): A fp16 convert
#define NB_K0 (4 * NLB)            // 84
#define NB_BH ((DIN / 32) * (HH / 32))  // 2048
#define NB_AH ((int)(((size_t)MM * DIN / 8) / 256))  // 32768
#define PRO_BLOCKS (NB_K0 + NB_BH + NB_AH)

__global__ __launch_bounds__(256) void kpro(const float* __restrict__ X,
                                            const float* __restrict__ W,
                                            const float* __restrict__ lt,
                                            const float* __restrict__ wl) {
    const int bid = blockIdx.x;
    const int tid = threadIdx.x;

    if (bid < NB_K0) {
        // ---- label_h = label_table @ W_lab, 4 accumulators ----
        const int n = bid >> 2;
        const int h = (bid & 3) * 256 + tid;
        const float* ltr = lt + n * EE;
        float a0 = 0.f, a1 = 0.f, a2 = 0.f, a3 = 0.f;
        #pragma unroll 4
        for (int e = 0; e < EE; e += 4) {
            a0 = fmaf(ltr[e],     wl[(size_t)(e)     * HH + h], a0);
            a1 = fmaf(ltr[e + 1], wl[(size_t)(e + 1) * HH + h], a1);
            a2 = fmaf(ltr[e + 2], wl[(size_t)(e + 2) * HH + h], a2);
            a3 = fmaf(ltr[e + 3], wl[(size_t)(e + 3) * HH + h], a3);
        }
        g_labelh[n * HH + h] = (a0 + a1) + (a2 + a3);
    } else if (bid < NB_K0 + NB_BH) {
        // ---- B transpose + fp16 convert ----
        __shared__ float tile[32][33];
        const int idx = bid - NB_K0;
        const int kb = (idx & 63) * 32, nb = (idx >> 6) * 32;
        const int tx = tid & 31, ty = tid >> 5;   // 32 x 8
        #pragma unroll
        for (int i = 0; i < 32; i += 8)
            tile[ty + i][tx] = W[(size_t)(kb + ty + i) * HH + nb + tx];
        __syncthreads();
        #pragma unroll
        for (int i = 0; i < 32; i += 8)
            g_bf16[(size_t)(nb + ty + i) * DIN + kb + tx] = __float2half(tile[tx][ty + i]);
    } else {
        // ---- A convert fp32 -> fp16 ----
        const size_t i = ((size_t)(bid - NB_K0 - NB_BH) * 256 + tid) * 8;
        const float4 v0 = *(const float4*)(X + i);
        const float4 v1 = *(const float4*)(X + i + 4);
        __half2 h[4];
        h[0] = __floats2half2_rn(v0.x, v0.y);
        h[1] = __floats2half2_rn(v0.z, v0.w);
        h[2] = __floats2half2_rn(v1.x, v1.y);
        h[3] = __floats2half2_rn(v1.z, v1.w);
        *(uint4*)(g_af16 + i) = *(uint4*)h;
    }
}

// ---------------- K1: fp16 GEMM, 128x256 tile, 512 thr, KC=64, 3-stage ----------------
#define KC 64
#define NCH (DIN / KC)        // 32
#define TP 144                // smem row pitch bytes (9*16B)
#define TILEA (128 * TP)      // 18432
#define TILEB (256 * TP)      // 36864
#define STAGE (TILEA + TILEB) // 55296
#define NST 3

// issue q-iterations [q0, q0+2) of the 6-iteration copy schedule
__device__ __forceinline__ void prefetch_pair(uint32_t sbuf, int cRow, int cCol,
                                              int k0, int tid, int q0) {
    #pragma unroll
    for (int qq = 0; qq < 2; qq++) {
        const int id = (q0 + qq) * 512 + tid;   // 0..3071
        const int seg = id & 7;
        if (id < 1024) {                   // A: 128 rows x 8 segs
            const int r = id >> 3;
            CP16(sbuf + (uint32_t)(r * TP + seg * 16),
                 g_af16 + (size_t)(cRow + r) * DIN + k0 + seg * 8);
        } else {                           // B: 256 rows x 8 segs
            const int r = (id - 1024) >> 3;
            CP16(sbuf + (uint32_t)TILEA + (uint32_t)(r * TP + seg * 16),
                 g_bf16 + (size_t)(cCol + r) * DIN + k0 + seg * 8);
        }
    }
}

__global__ __launch_bounds__(512, 1) void k1_mma() {
    extern __shared__ char sm[];
    const int tid = threadIdx.x, lane = tid & 31, wid = tid >> 5;
    const int cCol = blockIdx.x * 256, cRow = blockIdx.y * 128;
    const int wm = wid >> 2, wn = wid & 3;  // warp tile 32M x 64N
    const uint32_t sb = smem_u32(sm);

    float acc[2][8][4];
    #pragma unroll
    for (int i = 0; i < 2; i++)
        #pragma unroll
        for (int j = 0; j < 8; j++)
            #pragma unroll
            for (int k = 0; k < 4; k++) acc[i][j][k] = 0.f;

    // prologue: stage chunks 0 and 1 as separate groups
    prefetch_pair(sb, cRow, cCol, 0, tid, 0);
    prefetch_pair(sb, cRow, cCol, 0, tid, 2);
    prefetch_pair(sb, cRow, cCol, 0, tid, 4);
    CP_COMMIT();
    prefetch_pair(sb + STAGE, cRow, cCol, KC, tid, 0);
    prefetch_pair(sb + STAGE, cRow, cCol, KC, tid, 2);
    prefetch_pair(sb + STAGE, cRow, cCol, KC, tid, 4);
    CP_COMMIT();

    const int aRow = wm * 32 + (lane & 15);            // + mt*16
    const uint32_t aKb = (uint32_t)((lane >> 4) * 16); // + ks*32
    const int bRow = wn * 64 + ((lane >> 4) & 1) * 8 + (lane & 7); // + p*16
    const uint32_t bKb = (uint32_t)(((lane >> 3) & 1) * 16);

    int stage = 0;
    for (int c = 0; c < NCH; c++) {
        if (c + 1 < NCH) {
            asm volatile("cp.async.wait_group 1;" ::: "memory");
        } else {
            asm volatile("cp.async.wait_group 0;" ::: "memory");
        }
        __syncthreads();
        const uint32_t stA = sb + (uint32_t)(stage * STAGE);
        const uint32_t stB = stA + (uint32_t)TILEA;
        const bool pf = (c + 2 < NCH);
        int ps = stage + 2; if (ps >= NST) ps -= NST;
        const uint32_t nbuf = sb + (uint32_t)(ps * STAGE);
        const int nk0 = (c + 2) * KC;

        #pragma unroll
        for (int ks = 0; ks < 4; ks++) {
            // spread chunk c+2 copy issue across the MMA work
            if (pf && ks < 3) prefetch_pair(nbuf, cRow, cCol, nk0, tid, ks * 2);

            uint32_t ah[2][4];
            #pragma unroll
            for (int mt = 0; mt < 2; mt++) {
                const uint32_t ao = stA + (uint32_t)((aRow + mt * 16) * TP) + aKb
                                  + (uint32_t)(ks * 32);
                LDSM_X4(ah[mt][0], ah[mt][1], ah[mt][2], ah[mt][3], ao);
            }
            #pragma unroll
            for (int p = 0; p < 4; p++) {
                const uint32_t bo = stB + (uint32_t)((bRow + p * 16) * TP) + bKb
                                  + (uint32_t)(ks * 32);
                uint32_t b0, b1, b2, b3;
                LDSM_X4(b0, b1, b2, b3, bo);
                #pragma unroll
                for (int mt = 0; mt < 2; mt++) {
                    MMAH(acc[mt][2*p],   ah[mt][0], ah[mt][1], ah[mt][2], ah[mt][3], b0, b1);
                    MMAH(acc[mt][2*p+1], ah[mt][0], ah[mt][1], ah[mt][2], ah[mt][3], b2, b3);
                }
            }
            if (pf && ks == 2) CP_COMMIT();
        }
        stage = (stage + 1 == NST) ? 0 : stage + 1;
    }

    #pragma unroll
    for (int mt = 0; mt < 2; mt++)
        #pragma unroll
        for (int nt = 0; nt < 8; nt++) {
            const int row = cRow + wm * 32 + mt * 16 + (lane >> 2);
            const int col = cCol + wn * 64 + nt * 8 + (lane & 3) * 2;
            float2 v0 = make_float2(acc[mt][nt][0], acc[mt][nt][1]);
            float2 v1 = make_float2(acc[mt][nt][2], acc[mt][nt][3]);
            *(float2*)&g_h[(size_t)row * HH + col] = v0;
            *(float2*)&g_h[(size_t)(row + 8) * HH + col] = v1;
        }
}

// ---------------- K2: warp-per-row LN + exact GELU + logits + rowmax (fp16 table) ----------------
__global__ __launch_bounds__(256)
void k2_fused(const float* __restrict__ gamma, const float* __restrict__ beta,
              const float* __restrict__ temp_p, float* __restrict__ logits) {
    extern __shared__ char smraw[];
    uint4* slh8 = (uint4*)smraw;           // NLB*HH halves as half8 chunks (NLB*128)
    const int tid = threadIdx.x, lane = tid & 31, wid = tid >> 5;

    // convert label table fp32 -> fp16 into smem
    const float4* lh4 = (const float4*)g_labelh;
    for (int i = tid; i < NLB * HH / 8; i += 256) {
        const float4 a = lh4[2 * i], b = lh4[2 * i + 1];
        __half2 h[4];
        h[0] = __floats2half2_rn(a.x, a.y);
        h[1] = __floats2half2_rn(a.z, a.w);
        h[2] = __floats2half2_rn(b.x, b.y);
        h[3] = __floats2half2_rn(b.z, b.w);
        slh8[i] = *(uint4*)h;
    }
    const float tempv = *temp_p;
    const float4* gamma4 = (const float4*)gamma;
    const float4* beta4  = (const float4*)beta;
    __syncthreads();

    const int rowbase = blockIdx.x * 64 + wid * 8;
    for (int r = 0; r < 8; r++) {
        const int row = rowbase + r;
        const float4* hr4 = (const float4*)(g_h + (size_t)row * HH);
        // lane owns elements [8*lane + 256*q4, +8) for q4 in 0..3
        float4 xv[8];
        #pragma unroll
        for (int q4 = 0; q4 < 4; q4++) {
            xv[2*q4]   = hr4[lane * 2 + 64 * q4];
            xv[2*q4+1] = hr4[lane * 2 + 64 * q4 + 1];
        }

        float s = 0.f, ss = 0.f;
        #pragma unroll
        for (int q = 0; q < 8; q++) {
            s  += xv[q].x + xv[q].y + xv[q].z + xv[q].w;
            ss += xv[q].x*xv[q].x + xv[q].y*xv[q].y + xv[q].z*xv[q].z + xv[q].w*xv[q].w;
        }
        #pragma unroll
        for (int o = 16; o > 0; o >>= 1) {
            s  += __shfl_xor_sync(0xffffffffu, s, o);
            ss += __shfl_xor_sync(0xffffffffu, ss, o);
        }
        const float mean = s * (1.f / HH);
        const float rstd = rsqrtf(ss * (1.f / HH) - mean * mean + LN_EPS);

        // GELU into t[32]  (gamma/beta index MATCHES xv: lane*2 + 64*(q>>1) + (q&1))
        float t[32];
        #pragma unroll
        for (int q = 0; q < 8; q++) {
            const int gi = lane * 2 + 64 * (q >> 1) + (q & 1);
            const float4 g4 = gamma4[gi];
            const float4 b4 = beta4[gi];
            float y0 = (xv[q].x - mean) * rstd * g4.x + b4.x;
            float y1 = (xv[q].y - mean) * rstd * g4.y + b4.y;
            float y2 = (xv[q].z - mean) * rstd * g4.z + b4.z;
            float y3 = (xv[q].w - mean) * rstd * g4.w + b4.w;
            t[q*4+0] = 0.5f * y0 * (1.f + erff(y0 * 0.70710678118654752f));
            t[q*4+1] = 0.5f * y1 * (1.f + erff(y1 * 0.70710678118654752f));
            t[q*4+2] = 0.5f * y2 * (1.f + erff(y2 * 0.70710678118654752f));
            t[q*4+3] = 0.5f * y3 * (1.f + erff(y3 * 0.70710678118654752f));
        }

        float acc[NLB];
        #pragma unroll
        for (int l = 0; l < NLB; l++) acc[l] = 0.f;

        #pragma unroll
        for (int q4 = 0; q4 < 4; q4++) {
            const float* tq = t + q4 * 8;
            #pragma unroll
            for (int l = 0; l < NLB; l++) {
                const uint4 w = slh8[l * 128 + lane + 32 * q4];
                const __half2* wh = (const __half2*)&w;
                const float2 f0 = __half22float2(wh[0]);
                const float2 f1 = __half22float2(wh[1]);
                const float2 f2 = __half22float2(wh[2]);
                const float2 f3 = __half22float2(wh[3]);
                float a0 = fmaf(tq[0], f0.x, tq[1] * f0.y);
                float a1 = fmaf(tq[2], f1.x, tq[3] * f1.y);
                float a2 = fmaf(tq[4], f2.x, tq[5] * f2.y);
                float a3 = fmaf(tq[6], f3.x, tq[7] * f3.y);
                acc[l] += (a0 + a1) + (a2 + a3);
            }
        }

        float out = 0.f;
        #pragma unroll
        for (int l = 0; l < NLB; l++) {
            float v = acc[l];
            #pragma unroll
            for (int o = 16; o > 0; o >>= 1) v += __shfl_xor_sync(0xffffffffu, v, o);
            if (lane == l) out = v * tempv;
        }
        if (lane < NLB) logits[(size_t)row * NLB + lane] = out;
        float mv = (lane < NLB) ? out : -INFINITY;
        #pragma unroll
        for (int o = 16; o > 0; o >>= 1) mv = fmaxf(mv, __shfl_xor_sync(0xffffffffu, mv, o));
        if (lane == 0) g_rowmax[row] = mv;
    }
}

// ---------------- K3: CRF forward, cp.async-staged, exp domain, renorm /8 ----------------
#define CRF_CH 32
#define CRF_NC (LL / CRF_CH)
#define CRF_FB (CRF_CH * NLB)
#define CRF_BF (CRF_FB + CRF_CH)

__global__ void k3_crf(const float* __restrict__ logits, const int* __restrict__ labels,
                       const float* __restrict__ start_t, const float* __restrict__ end_t,
                       const float* __restrict__ trans) {
    __shared__ __align__(16) float sbuf[3][CRF_BF];
    const int b = blockIdx.x;
    const int j = threadIdx.x;  // 32 lanes
    float eT[NLB];
    #pragma unroll
    for (int i = 0; i < NLB; i++) eT[i] = (j < NLB) ? expf(trans[i * NLB + j]) : 0.f;

    const float* lg = logits + (size_t)b * LL * NLB;
    const float* rm = g_rowmax + (size_t)b * LL;
    const int* lab = labels + (size_t)b * LL;

    const char* lgB = (const char*)lg;
    const char* rmB = (const char*)rm;

    #pragma unroll
    for (int cc = 0; cc < 2; cc++) {
        const uint32_t dst = smem_u32(&sbuf[cc][0]);
        for (int u = j; u < 176; u += 32) {
            const char* src = (u < 168) ? (lgB + cc * 2688 + u * 16)
                                        : (rmB + cc * 128 + (u - 168) * 16);
            CP16(dst + u * 16, src);
        }
        CP_COMMIT();
    }

    float f = 0.f, logc = 0.f;

    for (int c = 0; c < CRF_NC; c++) {
        if (c + 2 < CRF_NC) {
            const int nc = c + 2;
            const uint32_t dst = smem_u32(&sbuf[nc % 3][0]);
            for (int u = j; u < 176; u += 32) {
                const char* src = (u < 168) ? (lgB + nc * 2688 + u * 16)
                                            : (rmB + nc * 128 + (u - 168) * 16);
                CP16(dst + u * 16, src);
            }
            CP_COMMIT();
            asm volatile("cp.async.wait_group 2;" ::: "memory");
        } else if (c + 1 < CRF_NC) {
            asm volatile("cp.async.wait_group 1;" ::: "memory");
        } else {
            asm volatile("cp.async.wait_group 0;" ::: "memory");
        }
        __syncwarp();
        const float* sc = sbuf[c % 3];

        int w0 = 0;
        if (c == 0) {
            float a0 = (j < NLB) ? (start_t[j] + sc[j]) : -INFINITY;
            float m = a0;
            #pragma unroll
            for (int o = 16; o > 0; o >>= 1) m = fmaxf(m, __shfl_xor_sync(0xffffffffu, m, o));
            f = expf(a0 - m);
            logc = m;
            w0 = 1;
        }

        #pragma unroll 4
        for (int w = w0; w < CRF_CH; w++) {
            const int t = c * CRF_CH + w;
            const float e = (j < NLB) ? sc[w * NLB + j] : -1e30f;
            const float mt = sc[CRF_FB + w];
            float g0 = 0.f, g1 = 0.f, g2 = 0.f;
            #pragma unroll
            for (int i = 0; i < NLB; i += 3) {
                g0 = fmaf(__shfl_sync(0xffffffffu, f, i),     eT[i],     g0);
                g1 = fmaf(__shfl_sync(0xffffffffu, f, i + 1), eT[i + 1], g1);
                g2 = fmaf(__shfl_sync(0xffffffffu, f, i + 2), eT[i + 2], g2);
            }
            float fn = ((g0 + g1) + g2) * __expf(e - mt);
            logc += mt;
            if ((t & 7) == 7) {
                float mx = fn;
                #pragma unroll
                for (int o = 16; o > 0; o >>= 1) mx = fmaxf(mx, __shfl_xor_sync(0xffffffffu, mx, o));
                fn = fn / mx;
                logc += logf(mx);
            }
            f = fn;
        }
        __syncwarp();
    }

    float sf = (j < NLB) ? f * expf(end_t[j]) : 0.f;
    #pragma unroll
    for (int o = 16; o > 0; o >>= 1) sf += __shfl_xor_sync(0xffffffffu, sf, o);
    const float logZ = logc + logf(sf);

    float sc2 = 0.f;
    for (int t = j; t < LL; t += 32) {
        const int lt_ = lab[t];
        sc2 += lg[t * NLB + lt_];
        if (t >= 1) sc2 += trans[lab[t - 1] * NLB + lt_];
    }
    #pragma unroll
    for (int o = 16; o > 0; o >>= 1) sc2 += __shfl_xor_sync(0xffffffffu, sc2, o);
    if (j == 0) {
        sc2 += start_t[lab[0]] + end_t[lab[LL - 1]];
        g_nll[b] = logZ - sc2;
    }
}

// ---------------- K4: loss ----------------
__global__ void k4_loss(float* __restrict__ out_loss) {
    float v = g_nll[threadIdx.x];
    #pragma unroll
    for (int o = 16; o > 0; o >>= 1) v += __shfl_xor_sync(0xffffffffu, v, o);
    if (threadIdx.x == 0) *out_loss = v * (1.f / BB);
}

extern "C" void kernel_launch(void* const* d_in, const int* in_sizes, int n_in,
                              void* d_out, int out_size) {
    const float* seq    = (const float*)d_in[0];
    const int*   labels = (const int*)  d_in[1];
    const float* Wtok   = (const float*)d_in[3];
    const float* gamma  = (const float*)d_in[4];
    const float* beta   = (const float*)d_in[5];
    const float* ltab   = (const float*)d_in[6];
    const float* Wlab   = (const float*)d_in[7];
    const float* temp   = (const float*)d_in[8];
    const float* startt = (const float*)d_in[9];
    const float* endt   = (const float*)d_in[10];
    const float* trans  = (const float*)d_in[11];
    float* out = (float*)d_out;

    kpro<<<PRO_BLOCKS, 256>>>(seq, Wtok, ltab, Wlab);

    const int smem1 = NST * STAGE;   // 165888
    cudaFuncSetAttribute(k1_mma, cudaFuncAttributeMaxDynamicSharedMemorySize, smem1);
    k1_mma<<<dim3(HH / 256, MM / 128), 512, smem1>>>();

    const int smem2 = NLB * HH * (int)sizeof(__half);   // 43008
    cudaFuncSetAttribute(k2_fused, cudaFuncAttributeMaxDynamicSharedMemorySize, smem2);
    k2_fused<<<MM / 64, 256, smem2>>>(gamma, beta, temp, out);

    k3_crf<<<BB, 32>>>(out, labels, startt, endt, trans);
    k4_loss<<<1, 32>>>(out + (out_size - 1));
}

// round 17
// speedup vs baseline: 2.2828x; 1.0607x over previous
#include <cuda_runtime.h>
#include <cuda_fp16.h>
#include <math.h>
#include <stdint.h>

#define BB   32
#define LL   1024
#define DIN  2048
#define HH   1024
#define NLB  21
#define EE   768
#define MM   (BB*LL)
#define LN_EPS 1e-5f

// ---------------- device scratch ----------------
__device__ __align__(16) float g_h[(size_t)MM * HH];
__device__ __align__(16) __half g_af16[(size_t)MM * DIN];
__device__ __align__(16) __half g_bf16[(size_t)HH * DIN];   // [n][k]
__device__ __align__(16) float g_labelh[NLB * HH];
__device__ __align__(16) float g_rowmax[MM];
__device__ float g_nll[BB];

// ---------------- helpers ----------------
__device__ __forceinline__ uint32_t smem_u32(const void* p) {
    uint32_t a;
    asm("{ .reg .u64 t; cvta.to.shared.u64 t, %1; cvt.u32.u64 %0, t; }" : "=r"(a) : "l"(p));
    return a;
}
#define CP16(ds, sp) asm volatile("cp.async.cg.shared.global [%0], [%1], 16;" \
    :: "r"(ds), "l"(__cvta_generic_to_global(sp)) : "memory")
#define CP_COMMIT() asm volatile("cp.async.commit_group;" ::: "memory")
#define LDSM_X4(r0, r1, r2, r3, a) asm volatile( \
    "ldmatrix.sync.aligned.m8n8.x4.shared.b16 {%0,%1,%2,%3}, [%4];" \
    : "=r"(r0), "=r"(r1), "=r"(r2), "=r"(r3) : "r"(a))
#define MMAH(d, a0, a1, a2, a3, b0, b1) asm volatile( \
    "mma.sync.aligned.m16n8k16.row.col.f32.f16.f16.f32 " \
    "{%0,%1,%2,%3}, {%4,%5,%6,%7}, {%8,%9}, {%0,%1,%2,%3};" \
    : "+f"((d)[0]), "+f"((d)[1]), "+f"((d)[2]), "+f"((d)[3]) \
    : "r"(a0), "r"(a1), "r"(a2), "r"(a3), "r"(b0), "r"(b1))

// ---------------- Kpro: fused prologue ----------------
#define NB_K0 (4 * NLB)            // 84
#define NB_BH ((DIN / 32) * (HH / 32))  // 2048
#define NB_AH ((int)(((size_t)MM * DIN / 8) / 256))  // 32768
#define PRO_BLOCKS (NB_K0 + NB_BH + NB_AH)

__global__ __launch_bounds__(256) void kpro(const float* __restrict__ X,
                                            const float* __restrict__ W,
                                            const float* __restrict__ lt,
                                            const float* __restrict__ wl) {
    const int bid = blockIdx.x;
    const int tid = threadIdx.x;

    if (bid < NB_K0) {
        const int n = bid >> 2;
        const int h = (bid & 3) * 256 + tid;
        const float* ltr = lt + n * EE;
        float a0 = 0.f, a1 = 0.f, a2 = 0.f, a3 = 0.f;
        #pragma unroll 4
        for (int e = 0; e < EE; e += 4) {
            a0 = fmaf(ltr[e],     wl[(size_t)(e)     * HH + h], a0);
            a1 = fmaf(ltr[e + 1], wl[(size_t)(e + 1) * HH + h], a1);
            a2 = fmaf(ltr[e + 2], wl[(size_t)(e + 2) * HH + h], a2);
            a3 = fmaf(ltr[e + 3], wl[(size_t)(e + 3) * HH + h], a3);
        }
        g_labelh[n * HH + h] = (a0 + a1) + (a2 + a3);
    } else if (bid < NB_K0 + NB_BH) {
        __shared__ float tile[32][33];
        const int idx = bid - NB_K0;
        const int kb = (idx & 63) * 32, nb = (idx >> 6) * 32;
        const int tx = tid & 31, ty = tid >> 5;
        #pragma unroll
        for (int i = 0; i < 32; i += 8)
            tile[ty + i][tx] = W[(size_t)(kb + ty + i) * HH + nb + tx];
        __syncthreads();
        #pragma unroll
        for (int i = 0; i < 32; i += 8)
            g_bf16[(size_t)(nb + ty + i) * DIN + kb + tx] = __float2half(tile[tx][ty + i]);
    } else {
        const size_t i = ((size_t)(bid - NB_K0 - NB_BH) * 256 + tid) * 8;
        const float4 v0 = *(const float4*)(X + i);
        const float4 v1 = *(const float4*)(X + i + 4);
        __half2 h[4];
        h[0] = __floats2half2_rn(v0.x, v0.y);
        h[1] = __floats2half2_rn(v0.z, v0.w);
        h[2] = __floats2half2_rn(v1.x, v1.y);
        h[3] = __floats2half2_rn(v1.z, v1.w);
        *(uint4*)(g_af16 + i) = *(uint4*)h;
    }
}

// ---------------- K1: fp16 GEMM, 128x256 tile, 512 thr, KC=64, 3-stage ----------------
#define KC 64
#define NCH (DIN / KC)        // 32
#define TP 144                // smem row pitch bytes (9*16B)
#define TILEA (128 * TP)      // 18432
#define TILEB (256 * TP)      // 36864
#define STAGE (TILEA + TILEB) // 55296
#define NST 3

__device__ __forceinline__ void prefetch_pair(uint32_t sbuf, int cRow, int cCol,
                                              int k0, int tid, int q0) {
    #pragma unroll
    for (int qq = 0; qq < 2; qq++) {
        const int id = (q0 + qq) * 512 + tid;
        const int seg = id & 7;
        if (id < 1024) {
            const int r = id >> 3;
            CP16(sbuf + (uint32_t)(r * TP + seg * 16),
                 g_af16 + (size_t)(cRow + r) * DIN + k0 + seg * 8);
        } else {
            const int r = (id - 1024) >> 3;
            CP16(sbuf + (uint32_t)TILEA + (uint32_t)(r * TP + seg * 16),
                 g_bf16 + (size_t)(cCol + r) * DIN + k0 + seg * 8);
        }
    }
}

__global__ __launch_bounds__(512, 1) void k1_mma() {
    extern __shared__ char sm[];
    const int tid = threadIdx.x, lane = tid & 31, wid = tid >> 5;
    const int cCol = blockIdx.x * 256, cRow = blockIdx.y * 128;
    const int wm = wid >> 2, wn = wid & 3;
    const uint32_t sb = smem_u32(sm);

    float acc[2][8][4];
    #pragma unroll
    for (int i = 0; i < 2; i++)
        #pragma unroll
        for (int j = 0; j < 8; j++)
            #pragma unroll
            for (int k = 0; k < 4; k++) acc[i][j][k] = 0.f;

    prefetch_pair(sb, cRow, cCol, 0, tid, 0);
    prefetch_pair(sb, cRow, cCol, 0, tid, 2);
    prefetch_pair(sb, cRow, cCol, 0, tid, 4);
    CP_COMMIT();
    prefetch_pair(sb + STAGE, cRow, cCol, KC, tid, 0);
    prefetch_pair(sb + STAGE, cRow, cCol, KC, tid, 2);
    prefetch_pair(sb + STAGE, cRow, cCol, KC, tid, 4);
    CP_COMMIT();

    const int aRow = wm * 32 + (lane & 15);
    const uint32_t aKb = (uint32_t)((lane >> 4) * 16);
    const int bRow = wn * 64 + ((lane >> 4) & 1) * 8 + (lane & 7);
    const uint32_t bKb = (uint32_t)(((lane >> 3) & 1) * 16);

    int stage = 0;
    for (int c = 0; c < NCH; c++) {
        if (c + 1 < NCH) {
            asm volatile("cp.async.wait_group 1;" ::: "memory");
        } else {
            asm volatile("cp.async.wait_group 0;" ::: "memory");
        }
        __syncthreads();
        const uint32_t stA = sb + (uint32_t)(stage * STAGE);
        const uint32_t stB = stA + (uint32_t)TILEA;
        const bool pf = (c + 2 < NCH);
        int ps = stage + 2; if (ps >= NST) ps -= NST;
        const uint32_t nbuf = sb + (uint32_t)(ps * STAGE);
        const int nk0 = (c + 2) * KC;

        #pragma unroll
        for (int ks = 0; ks < 4; ks++) {
            if (pf && ks < 3) prefetch_pair(nbuf, cRow, cCol, nk0, tid, ks * 2);

            uint32_t ah[2][4];
            #pragma unroll
            for (int mt = 0; mt < 2; mt++) {
                const uint32_t ao = stA + (uint32_t)((aRow + mt * 16) * TP) + aKb
                                  + (uint32_t)(ks * 32);
                LDSM_X4(ah[mt][0], ah[mt][1], ah[mt][2], ah[mt][3], ao);
            }
            #pragma unroll
            for (int p = 0; p < 4; p++) {
                const uint32_t bo = stB + (uint32_t)((bRow + p * 16) * TP) + bKb
                                  + (uint32_t)(ks * 32);
                uint32_t b0, b1, b2, b3;
                LDSM_X4(b0, b1, b2, b3, bo);
                #pragma unroll
                for (int mt = 0; mt < 2; mt++) {
                    MMAH(acc[mt][2*p],   ah[mt][0], ah[mt][1], ah[mt][2], ah[mt][3], b0, b1);
                    MMAH(acc[mt][2*p+1], ah[mt][0], ah[mt][1], ah[mt][2], ah[mt][3], b2, b3);
                }
            }
            if (pf && ks == 2) CP_COMMIT();
        }
        stage = (stage + 1 == NST) ? 0 : stage + 1;
    }

    #pragma unroll
    for (int mt = 0; mt < 2; mt++)
        #pragma unroll
        for (int nt = 0; nt < 8; nt++) {
            const int row = cRow + wm * 32 + mt * 16 + (lane >> 2);
            const int col = cCol + wn * 64 + nt * 8 + (lane & 3) * 2;
            float2 v0 = make_float2(acc[mt][nt][0], acc[mt][nt][1]);
            float2 v1 = make_float2(acc[mt][nt][2], acc[mt][nt][3]);
            *(float2*)&g_h[(size_t)row * HH + col] = v0;
            *(float2*)&g_h[(size_t)(row + 8) * HH + col] = v1;
        }
}

// ---------------- K2: warp-per-row LN + exact GELU + logits + rowmax (fp16 table) ----------------
__global__ __launch_bounds__(256)
void k2_fused(const float* __restrict__ gamma, const float* __restrict__ beta,
              const float* __restrict__ temp_p, float* __restrict__ logits) {
    extern __shared__ char smraw[];
    uint4* slh8 = (uint4*)smraw;
    const int tid = threadIdx.x, lane = tid & 31, wid = tid >> 5;

    const float4* lh4 = (const float4*)g_labelh;
    for (int i = tid; i < NLB * HH / 8; i += 256) {
        const float4 a = lh4[2 * i], b = lh4[2 * i + 1];
        __half2 h[4];
        h[0] = __floats2half2_rn(a.x, a.y);
        h[1] = __floats2half2_rn(a.z, a.w);
        h[2] = __floats2half2_rn(b.x, b.y);
        h[3] = __floats2half2_rn(b.z, b.w);
        slh8[i] = *(uint4*)h;
    }
    const float tempv = *temp_p;
    const float4* gamma4 = (const float4*)gamma;
    const float4* beta4  = (const float4*)beta;
    __syncthreads();

    const int rowbase = blockIdx.x * 64 + wid * 8;
    for (int r = 0; r < 8; r++) {
        const int row = rowbase + r;
        const float4* hr4 = (const float4*)(g_h + (size_t)row * HH);
        float4 xv[8];
        #pragma unroll
        for (int q4 = 0; q4 < 4; q4++) {
            xv[2*q4]   = hr4[lane * 2 + 64 * q4];
            xv[2*q4+1] = hr4[lane * 2 + 64 * q4 + 1];
        }

        float s = 0.f, ss = 0.f;
        #pragma unroll
        for (int q = 0; q < 8; q++) {
            s  += xv[q].x + xv[q].y + xv[q].z + xv[q].w;
            ss += xv[q].x*xv[q].x + xv[q].y*xv[q].y + xv[q].z*xv[q].z + xv[q].w*xv[q].w;
        }
        #pragma unroll
        for (int o = 16; o > 0; o >>= 1) {
            s  += __shfl_xor_sync(0xffffffffu, s, o);
            ss += __shfl_xor_sync(0xffffffffu, ss, o);
        }
        const float mean = s * (1.f / HH);
        const float rstd = rsqrtf(ss * (1.f / HH) - mean * mean + LN_EPS);

        float t[32];
        #pragma unroll
        for (int q = 0; q < 8; q++) {
            const int gi = lane * 2 + 64 * (q >> 1) + (q & 1);
            const float4 g4 = gamma4[gi];
            const float4 b4 = beta4[gi];
            float y0 = (xv[q].x - mean) * rstd * g4.x + b4.x;
            float y1 = (xv[q].y - mean) * rstd * g4.y + b4.y;
            float y2 = (xv[q].z - mean) * rstd * g4.z + b4.z;
            float y3 = (xv[q].w - mean) * rstd * g4.w + b4.w;
            t[q*4+0] = 0.5f * y0 * (1.f + erff(y0 * 0.70710678118654752f));
            t[q*4+1] = 0.5f * y1 * (1.f + erff(y1 * 0.70710678118654752f));
            t[q*4+2] = 0.5f * y2 * (1.f + erff(y2 * 0.70710678118654752f));
            t[q*4+3] = 0.5f * y3 * (1.f + erff(y3 * 0.70710678118654752f));
        }

        float acc[NLB];
        #pragma unroll
        for (int l = 0; l < NLB; l++) acc[l] = 0.f;

        #pragma unroll
        for (int q4 = 0; q4 < 4; q4++) {
            const float* tq = t + q4 * 8;
            #pragma unroll
            for (int l = 0; l < NLB; l++) {
                const uint4 w = slh8[l * 128 + lane + 32 * q4];
                const __half2* wh = (const __half2*)&w;
                const float2 f0 = __half22float2(wh[0]);
                const float2 f1 = __half22float2(wh[1]);
                const float2 f2 = __half22float2(wh[2]);
                const float2 f3 = __half22float2(wh[3]);
                float a0 = fmaf(tq[0], f0.x, tq[1] * f0.y);
                float a1 = fmaf(tq[2], f1.x, tq[3] * f1.y);
                float a2 = fmaf(tq[4], f2.x, tq[5] * f2.y);
                float a3 = fmaf(tq[6], f3.x, tq[7] * f3.y);
                acc[l] += (a0 + a1) + (a2 + a3);
            }
        }

        float out = 0.f;
        #pragma unroll
        for (int l = 0; l < NLB; l++) {
            float v = acc[l];
            #pragma unroll
            for (int o = 16; o > 0; o >>= 1) v += __shfl_xor_sync(0xffffffffu, v, o);
            if (lane == l) out = v * tempv;
        }
        if (lane < NLB) logits[(size_t)row * NLB + lane] = out;
        float mv = (lane < NLB) ? out : -INFINITY;
        #pragma unroll
        for (int o = 16; o > 0; o >>= 1) mv = fmaxf(mv, __shfl_xor_sync(0xffffffffu, mv, o));
        if (lane == 0) g_rowmax[row] = mv;
    }
}

// ---------------- K3: CRF forward, staged + 2-phase chunks, renorm /16 ----------------
#define CRF_CH 32
#define CRF_NC (LL / CRF_CH)
#define CRF_FB (CRF_CH * NLB)
#define CRF_BF (CRF_FB + CRF_CH)

__global__ void k3_crf(const float* __restrict__ logits, const int* __restrict__ labels,
                       const float* __restrict__ start_t, const float* __restrict__ end_t,
                       const float* __restrict__ trans) {
    __shared__ __align__(16) float sbuf[3][CRF_BF];
    const int b = blockIdx.x;
    const int j = threadIdx.x;  // 32 lanes
    float eT[NLB];
    #pragma unroll
    for (int i = 0; i < NLB; i++) eT[i] = (j < NLB) ? expf(trans[i * NLB + j]) : 0.f;

    const float* lg = logits + (size_t)b * LL * NLB;
    const float* rm = g_rowmax + (size_t)b * LL;
    const int* lab = labels + (size_t)b * LL;

    const char* lgB = (const char*)lg;
    const char* rmB = (const char*)rm;

    #pragma unroll
    for (int cc = 0; cc < 2; cc++) {
        const uint32_t dst = smem_u32(&sbuf[cc][0]);
        for (int u = j; u < 176; u += 32) {
            const char* src = (u < 168) ? (lgB + cc * 2688 + u * 16)
                                        : (rmB + cc * 128 + (u - 168) * 16);
            CP16(dst + u * 16, src);
        }
        CP_COMMIT();
    }

    float f = 0.f, logc = 0.f;

    for (int c = 0; c < CRF_NC; c++) {
        if (c + 2 < CRF_NC) {
            const int nc = c + 2;
            const uint32_t dst = smem_u32(&sbuf[nc % 3][0]);
            for (int u = j; u < 176; u += 32) {
                const char* src = (u < 168) ? (lgB + nc * 2688 + u * 16)
                                            : (rmB + nc * 128 + (u - 168) * 16);
                CP16(dst + u * 16, src);
            }
            CP_COMMIT();
            asm volatile("cp.async.wait_group 2;" ::: "memory");
        } else if (c + 1 < CRF_NC) {
            asm volatile("cp.async.wait_group 1;" ::: "memory");
        } else {
            asm volatile("cp.async.wait_group 0;" ::: "memory");
        }
        __syncwarp();
        const float* sc = sbuf[c % 3];

        // ---- phase 1: precompute per-step scales s[w] and chunk mt-sum ----
        float s[CRF_CH];
        float msum = 0.f;
        #pragma unroll
        for (int w = 0; w < CRF_CH; w++) {
            const float e = (j < NLB) ? sc[w * NLB + j] : -1e30f;
            const float mt = sc[CRF_FB + w];
            s[w] = __expf(e - mt);
            msum += mt;
        }

        int w0 = 0;
        if (c == 0) {
            float a0 = (j < NLB) ? (start_t[j] + sc[j]) : -INFINITY;
            float m = a0;
            #pragma unroll
            for (int o = 16; o > 0; o >>= 1) m = fmaxf(m, __shfl_xor_sync(0xffffffffu, m, o));
            f = expf(a0 - m);
            logc = m - sc[CRF_FB];   // cancel msum's inclusion of mt[0]
            w0 = 1;
        }

        // ---- phase 2: pure shuffle/FMA recurrence ----
        #pragma unroll
        for (int w = 0; w < CRF_CH; w++) {
            if (w < w0) continue;
            float g0 = 0.f, g1 = 0.f, g2 = 0.f;
            #pragma unroll
            for (int i = 0; i < NLB; i += 3) {
                g0 = fmaf(__shfl_sync(0xffffffffu, f, i),     eT[i],     g0);
                g1 = fmaf(__shfl_sync(0xffffffffu, f, i + 1), eT[i + 1], g1);
                g2 = fmaf(__shfl_sync(0xffffffffu, f, i + 2), eT[i + 2], g2);
            }
            float fn = ((g0 + g1) + g2) * s[w];
            if ((w & 15) == 15) {
                float mx = fn;
                #pragma unroll
                for (int o = 16; o > 0; o >>= 1) mx = fmaxf(mx, __shfl_xor_sync(0xffffffffu, mx, o));
                fn = fn / mx;
                logc += __logf(mx);
            }
            f = fn;
        }
        logc += msum;
        __syncwarp();
    }

    float sf = (j < NLB) ? f * expf(end_t[j]) : 0.f;
    #pragma unroll
    for (int o = 16; o > 0; o >>= 1) sf += __shfl_xor_sync(0xffffffffu, sf, o);
    const float logZ = logc + logf(sf);

    float sc2 = 0.f;
    for (int t = j; t < LL; t += 32) {
        const int lt_ = lab[t];
        sc2 += lg[t * NLB + lt_];
        if (t >= 1) sc2 += trans[lab[t - 1] * NLB + lt_];
    }
    #pragma unroll
    for (int o = 16; o > 0; o >>= 1) sc2 += __shfl_xor_sync(0xffffffffu, sc2, o);
    if (j == 0) {
        sc2 += start_t[lab[0]] + end_t[lab[LL - 1]];
        g_nll[b] = logZ - sc2;
    }
}

// ---------------- K4: loss ----------------
__global__ void k4_loss(float* __restrict__ out_loss) {
    float v = g_nll[threadIdx.x];
    #pragma unroll
    for (int o = 16; o > 0; o >>= 1) v += __shfl_xor_sync(0xffffffffu, v, o);
    if (threadIdx.x == 0) *out_loss = v * (1.f / BB);
}

extern "C" void kernel_launch(void* const* d_in, const int* in_sizes, int n_in,
                              void* d_out, int out_size) {
    const float* seq    = (const float*)d_in[0];
    const int*   labels = (const int*)  d_in[1];
    const float* Wtok   = (const float*)d_in[3];
    const float* gamma  = (const float*)d_in[4];
    const float* beta   = (const float*)d_in[5];
    const float* ltab   = (const float*)d_in[6];
    const float* Wlab   = (const float*)d_in[7];
    const float* temp   = (const float*)d_in[8];
    const float* startt = (const float*)d_in[9];
    const float* endt   = (const float*)d_in[10];
    const float* trans  = (const float*)d_in[11];
    float* out = (float*)d_out;

    kpro<<<PRO_BLOCKS, 256>>>(seq, Wtok, ltab, Wlab);

    const int smem1 = NST * STAGE;   // 165888
    cudaFuncSetAttribute(k1_mma, cudaFuncAttributeMaxDynamicSharedMemorySize, smem1);
    k1_mma<<<dim3(HH / 256, MM / 128), 512, smem1>>>();

    const int smem2 = NLB * HH * (int)sizeof(__half);   // 43008
    cudaFuncSetAttribute(k2_fused, cudaFuncAttributeMaxDynamicSharedMemorySize, smem2);
    k2_fused<<<MM / 64, 256, smem2>>>(gamma, beta, temp, out);

    k3_crf<<<BB, 32>>>(out, labels, startt, endt, trans);
    k4_loss<<<1, 32>>>(out + (out_size - 1));
}